// round 8
// baseline (speedup 1.0000x reference)
#include <cuda_runtime.h>
#include <cuda_bf16.h>
#include <math.h>
#include <stdint.h>

#define BB 4
#define TT 1024
#define DD 1024
#define HH 16
#define DKK 64
#define MROWS (BB*TT)   // 4096

// ---------------- scratch (static device globals) ----------------
__device__ __nv_bfloat16 g_Qh[BB*HH*TT*DKK], g_Ql[BB*HH*TT*DKK];
__device__ __nv_bfloat16 g_Kh[BB*HH*TT*DKK], g_Kl[BB*HH*TT*DKK];
__device__ __nv_bfloat16 g_Vh[BB*HH*TT*DKK], g_Vl[BB*HH*TT*DKK];
__device__ float g_vmean[BB*HH*DKK];
__device__ float g_c[BB];
__device__ float g_scale[BB];
__device__ __nv_bfloat16 g_xh[MROWS*DD], g_xl[MROWS*DD];
__device__ __nv_bfloat16 g_WhQ[DD*DD], g_WlQ[DD*DD];
__device__ __nv_bfloat16 g_WhK[DD*DD], g_WlK[DD*DD];
__device__ __nv_bfloat16 g_WhV[DD*DD], g_WlV[DD*DD];
__device__ __nv_bfloat16 g_WhO[DD*DD], g_WlO[DD*DD];
__device__ __nv_bfloat16 g_aH[MROWS*DD], g_aL[MROWS*DD];

// ---------------- PTX helpers (sm_80-era only) ----------------
__device__ __forceinline__ uint32_t smem_u32(const void* p) {
    uint32_t a;
    asm("{ .reg .u64 t; cvta.to.shared.u64 t, %1; cvt.u32.u64 %0, t; }" : "=r"(a) : "l"(p));
    return a;
}
#define CP_ASYNC16(dst, src) asm volatile("cp.async.cg.shared.global [%0], [%1], 16;" :: "r"(dst), "l"(src))
#define CP_COMMIT()          asm volatile("cp.async.commit_group;" ::: "memory")
#define CP_WAIT(n)           asm volatile("cp.async.wait_group %0;" :: "n"(n) : "memory")

__device__ __forceinline__ void ldsm_x4(uint32_t& r0, uint32_t& r1, uint32_t& r2, uint32_t& r3, uint32_t addr) {
    asm volatile("ldmatrix.sync.aligned.m8n8.x4.shared.b16 {%0,%1,%2,%3}, [%4];"
                 : "=r"(r0), "=r"(r1), "=r"(r2), "=r"(r3) : "r"(addr));
}
__device__ __forceinline__ void ldsm_x2(uint32_t& r0, uint32_t& r1, uint32_t addr) {
    asm volatile("ldmatrix.sync.aligned.m8n8.x2.shared.b16 {%0,%1}, [%2];"
                 : "=r"(r0), "=r"(r1) : "r"(addr));
}
__device__ __forceinline__ void ldsm_x2t(uint32_t& r0, uint32_t& r1, uint32_t addr) {
    asm volatile("ldmatrix.sync.aligned.m8n8.x2.trans.shared.b16 {%0,%1}, [%2];"
                 : "=r"(r0), "=r"(r1) : "r"(addr));
}
__device__ __forceinline__ void mma16816(float* d, const uint32_t* a, const uint32_t* b) {
    asm volatile("mma.sync.aligned.m16n8k16.row.col.f32.bf16.bf16.f32 "
                 "{%0,%1,%2,%3},{%4,%5,%6,%7},{%8,%9},{%0,%1,%2,%3};"
                 : "+f"(d[0]), "+f"(d[1]), "+f"(d[2]), "+f"(d[3])
                 : "r"(a[0]), "r"(a[1]), "r"(a[2]), "r"(a[3]), "r"(b[0]), "r"(b[1]));
}

// ---------------------------------------------------------------------------
// Split-bf16 warp-MMA GEMM: C[m,n] = sum_k A[m,k]*W[n,k] + bias[n]
// MODE 0: C fp32 rowmajor.  MODE 1: split-bf16 hi/lo scatter to [B,H,T,DK].
// ---------------------------------------------------------------------------
struct GemmArgs {
    const __nv_bfloat16 *Ah, *Al;
    const __nv_bfloat16 *Wh0, *Wl0, *Wh1, *Wl1, *Wh2, *Wl2;
    const float *b0, *b1, *b2;
    float *C0;                                       // MODE 0
    __nv_bfloat16 *Ch0, *Cl0, *Ch1, *Cl1, *Ch2, *Cl2; // MODE 1
};

__device__ __forceinline__ void load_stage(uint32_t sbase, int tid,
                                           const __nv_bfloat16* Ah, const __nv_bfloat16* Al,
                                           const __nv_bfloat16* Wh, const __nv_bfloat16* Wl,
                                           int bm, int bn, int k0) {
#pragma unroll
    for (int i = 0; i < 4; i++) {
        int g = tid + i * 256;
        int r = g >> 3;
        int c = g & 7;
        uint32_t sw = (uint32_t)(r * 128 + (((c ^ (r & 7))) << 4));
        size_t ga = (size_t)(bm + r) * 1024 + k0;
        size_t gw = (size_t)(bn + r) * 1024 + k0;
        CP_ASYNC16(sbase +     0 + sw, (const char*)(Ah + ga) + c * 16);
        CP_ASYNC16(sbase + 16384 + sw, (const char*)(Al + ga) + c * 16);
        CP_ASYNC16(sbase + 32768 + sw, (const char*)(Wh + gw) + c * 16);
        CP_ASYNC16(sbase + 49152 + sw, (const char*)(Wl + gw) + c * 16);
    }
}

// Term-swept MMA ordering: all 16 accumulators per term -> same-acc RAW
// dependency spacing = 16 instructions (vs 1 before).
__device__ __forceinline__ void compute_stage(uint32_t base, int wm, int wn, int lane,
                                              float acc[4][4][4]) {
    const uint32_t aH = base, aL = base + 16384, bH = base + 32768, bL = base + 49152;
    const int rA = wm + (lane & 15);
    const int hA = lane >> 4;
    const int rB = wn + (lane & 7);
    const int hB = (lane >> 3) & 1;
#pragma unroll
    for (int ks = 0; ks < 4; ks++) {
        uint32_t Af[4][4], Alf[4][4], Bf[4][2], Blf[4][2];
#pragma unroll
        for (int mt = 0; mt < 4; mt++) {
            int r = rA + mt * 16;
            uint32_t off = (uint32_t)(r * 128 + ((((ks * 2 + hA)) ^ (r & 7)) << 4));
            ldsm_x4(Af[mt][0], Af[mt][1], Af[mt][2], Af[mt][3], aH + off);
            ldsm_x4(Alf[mt][0], Alf[mt][1], Alf[mt][2], Alf[mt][3], aL + off);
        }
#pragma unroll
        for (int nt = 0; nt < 4; nt++) {
            int r = rB + nt * 8;
            uint32_t off = (uint32_t)(r * 128 + ((((ks * 2 + hB)) ^ (r & 7)) << 4));
            ldsm_x2(Bf[nt][0], Bf[nt][1], bH + off);
            ldsm_x2(Blf[nt][0], Blf[nt][1], bL + off);
        }
        // term 0: Ah*Bh
#pragma unroll
        for (int mt = 0; mt < 4; mt++)
#pragma unroll
            for (int nt = 0; nt < 4; nt++)
                mma16816(acc[mt][nt], Af[mt], Bf[nt]);
        // term 1: Ah*Bl
#pragma unroll
        for (int mt = 0; mt < 4; mt++)
#pragma unroll
            for (int nt = 0; nt < 4; nt++)
                mma16816(acc[mt][nt], Af[mt], Blf[nt]);
        // term 2: Al*Bh
#pragma unroll
        for (int mt = 0; mt < 4; mt++)
#pragma unroll
            for (int nt = 0; nt < 4; nt++)
                mma16816(acc[mt][nt], Alf[mt], Bf[nt]);
    }
}

template<int MODE>
__global__ __launch_bounds__(256)
void gemm_mma(GemmArgs args) {
    extern __shared__ char smem[];
    const int tid = threadIdx.x, wid = tid >> 5, lane = tid & 31;
    const int z = blockIdx.z;
    const __nv_bfloat16* Ah = args.Ah;
    const __nv_bfloat16* Al = args.Al;
    const __nv_bfloat16* Wh = (z == 0) ? args.Wh0 : (z == 1) ? args.Wh1 : args.Wh2;
    const __nv_bfloat16* Wl = (z == 0) ? args.Wl0 : (z == 1) ? args.Wl1 : args.Wl2;
    const float* bias = (z == 0) ? args.b0 : (z == 1) ? args.b1 : args.b2;
    __nv_bfloat16* Ch = (z == 0) ? args.Ch0 : (z == 1) ? args.Ch1 : args.Ch2;
    __nv_bfloat16* Cl = (z == 0) ? args.Cl0 : (z == 1) ? args.Cl1 : args.Cl2;

    const int bm = blockIdx.y * 128, bn = blockIdx.x * 128;
    const int wm = (wid >> 2) * 64, wn = (wid & 3) * 32;
    const uint32_t s0 = smem_u32(smem);

    float acc[4][4][4];
#pragma unroll
    for (int a = 0; a < 4; a++)
#pragma unroll
        for (int b = 0; b < 4; b++)
#pragma unroll
            for (int c = 0; c < 4; c++) acc[a][b][c] = 0.f;

    load_stage(s0, tid, Ah, Al, Wh, Wl, bm, bn, 0);
    CP_COMMIT();

    for (int kt = 0; kt < 16; kt++) {
        const int s = kt & 1;
        if (kt + 1 < 16) {
            load_stage(s0 + ((kt + 1) & 1) * 65536, tid, Ah, Al, Wh, Wl, bm, bn, (kt + 1) * 64);
            CP_COMMIT();
            CP_WAIT(1);
        } else {
            CP_WAIT(0);
        }
        __syncthreads();
        compute_stage(s0 + s * 65536, wm, wn, lane, acc);
        __syncthreads();
    }

    const int lr = lane >> 2, lc = (lane & 3) * 2;
#pragma unroll
    for (int mt = 0; mt < 4; mt++) {
#pragma unroll
        for (int nt = 0; nt < 4; nt++) {
            int c0 = bn + wn + nt * 8 + lc;
            float b0 = __ldg(bias + c0), b1 = __ldg(bias + c0 + 1);
            int r0 = bm + wm + mt * 16 + lr;
            int r1 = r0 + 8;
            float v00 = acc[mt][nt][0] + b0, v01 = acc[mt][nt][1] + b1;
            float v10 = acc[mt][nt][2] + b0, v11 = acc[mt][nt][3] + b1;
            if (MODE == 0) {
                *(float2*)(args.C0 + (size_t)r0 * 1024 + c0) = make_float2(v00, v01);
                *(float2*)(args.C0 + (size_t)r1 * 1024 + c0) = make_float2(v10, v11);
            } else {
                int h = c0 >> 6, dk = c0 & 63;
                size_t i0 = (((size_t)((r0 >> 10) * HH + h)) * TT + (r0 & 1023)) * DKK + dk;
                size_t i1 = (((size_t)((r1 >> 10) * HH + h)) * TT + (r1 & 1023)) * DKK + dk;
                __nv_bfloat162 h0 = __floats2bfloat162_rn(v00, v01);
                __nv_bfloat162 h1 = __floats2bfloat162_rn(v10, v11);
                *(__nv_bfloat162*)(Ch + i0) = h0;
                *(__nv_bfloat162*)(Ch + i1) = h1;
                *(__nv_bfloat162*)(Cl + i0) = __floats2bfloat162_rn(
                    v00 - __bfloat162float(h0.x), v01 - __bfloat162float(h0.y));
                *(__nv_bfloat162*)(Cl + i1) = __floats2bfloat162_rn(
                    v10 - __bfloat162float(h1.x), v11 - __bfloat162float(h1.y));
            }
        }
    }
}

// ---------------------------------------------------------------------------
__global__ void convert_hl(const float* __restrict__ src,
                           __nv_bfloat16* __restrict__ h,
                           __nv_bfloat16* __restrict__ l, int n4) {
    int i = blockIdx.x * 256 + threadIdx.x;
    if (i >= n4) return;
    float4 v = ((const float4*)src)[i];
    __nv_bfloat16 h0 = __float2bfloat16(v.x);
    __nv_bfloat16 h1 = __float2bfloat16(v.y);
    __nv_bfloat16 h2 = __float2bfloat16(v.z);
    __nv_bfloat16 h3 = __float2bfloat16(v.w);
    __nv_bfloat162 hp0; hp0.x = h0; hp0.y = h1;
    __nv_bfloat162 hp1; hp1.x = h2; hp1.y = h3;
    ((__nv_bfloat162*)h)[i * 2 + 0] = hp0;
    ((__nv_bfloat162*)h)[i * 2 + 1] = hp1;
    __nv_bfloat162 lp0, lp1;
    lp0.x = __float2bfloat16(v.x - __bfloat162float(h0));
    lp0.y = __float2bfloat16(v.y - __bfloat162float(h1));
    lp1.x = __float2bfloat16(v.z - __bfloat162float(h2));
    lp1.y = __float2bfloat16(v.w - __bfloat162float(h3));
    ((__nv_bfloat162*)l)[i * 2 + 0] = lp0;
    ((__nv_bfloat162*)l)[i * 2 + 1] = lp1;
}

// ---------------------------------------------------------------------------
__global__ void gate_kernel(const __nv_bfloat16* __restrict__ Qh,
                            const __nv_bfloat16* __restrict__ Ql,
                            const float* __restrict__ Wg1, const float* __restrict__ bg1,
                            const float* __restrict__ Wg2, const float* __restrict__ bg2,
                            float* __restrict__ c_out, float* __restrict__ scale_out,
                            float* __restrict__ u_out, int write_u) {
    int b = blockIdx.x;
    float s1 = 0.f, s2 = 0.f;
    for (int d = threadIdx.x; d < DD; d += 256) {
        size_t idx = ((size_t)(b*HH + (d >> 6)))*TT*DKK + (d & 63);
        float q = __bfloat162float(Qh[idx]) + __bfloat162float(Ql[idx]);
        s1 += q * Wg1[d];
        s2 += q * Wg2[d];
    }
#pragma unroll
    for (int off = 16; off >= 1; off >>= 1) {
        s1 += __shfl_xor_sync(0xffffffffu, s1, off);
        s2 += __shfl_xor_sync(0xffffffffu, s2, off);
    }
    __shared__ float r1[8], r2[8];
    int lane = threadIdx.x & 31, w = threadIdx.x >> 5;
    if (lane == 0) { r1[w] = s1; r2[w] = s2; }
    __syncthreads();
    if (threadIdx.x == 0) {
        float t1 = 0.f, t2 = 0.f;
        for (int i = 0; i < 8; i++) { t1 += r1[i]; t2 += r2[i]; }
        float z1 = t1 + bg1[0], z2 = t2 + bg2[0];
        float q1 = 1.f / (1.f + expf(-z1));
        float q2 = 1.f / (1.f + expf(-z2));
        float c = fminf(fmaxf(q1 * q2, 1e-8f), 1.0f);
        float tau = (c < 0.3f) ? (1.0f / c) : 1.0f;
        c_out[b] = c;
        scale_out[b] = 1.0f / (8.0f * tau);
        if (write_u) u_out[b] = 1.0f - c;
    }
}

// ---------------------------------------------------------------------------
__global__ void vmean_kernel(const __nv_bfloat16* __restrict__ Vh,
                             const __nv_bfloat16* __restrict__ Vl,
                             float* __restrict__ vmean) {
    __shared__ float sm[256];
    int bh = blockIdx.x, tid = threadIdx.x;
    int dk = tid & 63, part = tid >> 6;
    size_t base = (size_t)bh * TT * DKK;
    float s = 0.f;
    for (int t = part; t < TT; t += 4) {
        size_t i = base + (size_t)t * DKK + dk;
        s += __bfloat162float(Vh[i]) + __bfloat162float(Vl[i]);
    }
    sm[tid] = s;
    __syncthreads();
    if (part == 0)
        vmean[bh*DKK + dk] = (sm[dk] + sm[64+dk] + sm[128+dk] + sm[192+dk]) * (1.0f/1024.0f);
}

// ---------------------------------------------------------------------------
// Tensor-core flash attention. Block = 128 queries x (b,h). 8 warps x 16 rows.
// S = QhKh+QhKl+QlKh; PV = PhVh+PhVl+PlVh, term-swept in groups of 4 for
// accumulator-dependency spacing.
// ---------------------------------------------------------------------------
__global__ __launch_bounds__(256)
void attn_mma(const __nv_bfloat16* __restrict__ Qh, const __nv_bfloat16* __restrict__ Ql,
              const __nv_bfloat16* __restrict__ Kh, const __nv_bfloat16* __restrict__ Kl,
              const __nv_bfloat16* __restrict__ Vh, const __nv_bfloat16* __restrict__ Vl,
              const float* __restrict__ vmean,
              const float* __restrict__ c_arr, const float* __restrict__ scale_arr,
              __nv_bfloat16* __restrict__ outH, __nv_bfloat16* __restrict__ outL) {
    extern __shared__ char smem[];
    const int tid = threadIdx.x, wid = tid >> 5, lane = tid & 31;
    const int bh = blockIdx.y;
    const int b = bh >> 4, h = bh & 15;
    const int q0 = blockIdx.x * 128;
    const float scale = scale_arr[b];
    const float cg = c_arr[b];
    const size_t gbase = (size_t)bh * TT * DKK;

    const uint32_t s0 = smem_u32(smem);
    const uint32_t QH = s0, QL = s0 + 16384;
    const uint32_t ST = s0 + 32768;

#pragma unroll
    for (int i = 0; i < 8; i++) {
        int g = tid + i * 256;
        int arr = g >> 10;
        int rem = g & 1023;
        int r = rem >> 3, c = rem & 7;
        uint32_t sw = (uint32_t)(r * 128 + ((c ^ (r & 7)) << 4));
        const __nv_bfloat16* src = arr ? Ql : Qh;
        CP_ASYNC16((arr ? QL : QH) + sw, (const char*)(src + gbase + (size_t)(q0 + r) * 64) + c * 16);
    }
#pragma unroll
    for (int i = 0; i < 8; i++) {
        int g = tid + i * 256;
        int arr = g >> 9;
        int rem = g & 511;
        int r = rem >> 3, c = rem & 7;
        uint32_t sw = (uint32_t)(r * 128 + ((c ^ (r & 7)) << 4));
        const __nv_bfloat16* src = (arr == 0) ? Kh : (arr == 1) ? Kl : (arr == 2) ? Vh : Vl;
        CP_ASYNC16(ST + arr * 8192 + sw, (const char*)(src + gbase + (size_t)r * 64) + c * 16);
    }
    CP_COMMIT();

    const int rA = wid * 16 + (lane & 15);
    const int hA = lane >> 4;
    const int rB = lane & 7;
    const int hB = (lane >> 3) & 1;
    const int rV = lane & 15;

    uint32_t qhF[4][4], qlF[4][4];
    float O[8][4];
    float m0 = -1e30f, m1 = -1e30f, l0 = 0.f, l1 = 0.f;
#pragma unroll
    for (int nt = 0; nt < 8; nt++)
#pragma unroll
        for (int j = 0; j < 4; j++) O[nt][j] = 0.f;

    for (int kt = 0; kt < 16; kt++) {
        const uint32_t stage = ST + (kt & 1) * 32768;
        if (kt + 1 < 16) {
            const uint32_t nstage = ST + ((kt + 1) & 1) * 32768;
            const int k0n = (kt + 1) * 64;
#pragma unroll
            for (int i = 0; i < 8; i++) {
                int g = tid + i * 256;
                int arr = g >> 9;
                int rem = g & 511;
                int r = rem >> 3, c = rem & 7;
                uint32_t sw = (uint32_t)(r * 128 + ((c ^ (r & 7)) << 4));
                const __nv_bfloat16* src = (arr == 0) ? Kh : (arr == 1) ? Kl : (arr == 2) ? Vh : Vl;
                CP_ASYNC16(nstage + arr * 8192 + sw,
                           (const char*)(src + gbase + (size_t)(k0n + r) * 64) + c * 16);
            }
            CP_COMMIT();
            CP_WAIT(1);
        } else {
            CP_WAIT(0);
        }
        __syncthreads();

        if (kt == 0) {
#pragma unroll
            for (int ks = 0; ks < 4; ks++) {
                uint32_t off = (uint32_t)(rA * 128 + (((ks * 2 + hA) ^ (rA & 7)) << 4));
                ldsm_x4(qhF[ks][0], qhF[ks][1], qhF[ks][2], qhF[ks][3], QH + off);
                ldsm_x4(qlF[ks][0], qlF[ks][1], qlF[ks][2], qlF[ks][3], QL + off);
            }
        }

        // ---- S = Q K^T (3-term split, term-swept in groups of 4) ----
        float sacc[8][4];
#pragma unroll
        for (int nt = 0; nt < 8; nt++)
#pragma unroll
            for (int j = 0; j < 4; j++) sacc[nt][j] = 0.f;

        const uint32_t KHs = stage, KLs = stage + 8192;
#pragma unroll
        for (int ks = 0; ks < 4; ks++) {
#pragma unroll
            for (int g = 0; g < 2; g++) {
                uint32_t kh[4][2], kl[4][2];
#pragma unroll
                for (int j = 0; j < 4; j++) {
                    int r = (g * 4 + j) * 8 + rB;
                    uint32_t off = (uint32_t)(r * 128 + (((ks * 2 + hB) ^ (r & 7)) << 4));
                    ldsm_x2(kh[j][0], kh[j][1], KHs + off);
                    ldsm_x2(kl[j][0], kl[j][1], KLs + off);
                }
#pragma unroll
                for (int j = 0; j < 4; j++) mma16816(sacc[g*4+j], qhF[ks], kh[j]);
#pragma unroll
                for (int j = 0; j < 4; j++) mma16816(sacc[g*4+j], qhF[ks], kl[j]);
#pragma unroll
                for (int j = 0; j < 4; j++) mma16816(sacc[g*4+j], qlF[ks], kh[j]);
            }
        }

        // ---- online softmax ----
        float mx0 = -1e30f, mx1 = -1e30f;
#pragma unroll
        for (int nt = 0; nt < 8; nt++) {
            mx0 = fmaxf(mx0, fmaxf(sacc[nt][0], sacc[nt][1]));
            mx1 = fmaxf(mx1, fmaxf(sacc[nt][2], sacc[nt][3]));
        }
        mx0 = fmaxf(mx0, __shfl_xor_sync(0xffffffffu, mx0, 1));
        mx0 = fmaxf(mx0, __shfl_xor_sync(0xffffffffu, mx0, 2));
        mx1 = fmaxf(mx1, __shfl_xor_sync(0xffffffffu, mx1, 1));
        mx1 = fmaxf(mx1, __shfl_xor_sync(0xffffffffu, mx1, 2));
        float mn0 = fmaxf(m0, mx0 * scale);
        float mn1 = fmaxf(m1, mx1 * scale);
        float f0 = __expf(m0 - mn0), f1 = __expf(m1 - mn1);
        m0 = mn0; m1 = mn1;

        float rs0 = 0.f, rs1 = 0.f;
#pragma unroll
        for (int nt = 0; nt < 8; nt++) {
            sacc[nt][0] = __expf(fmaf(sacc[nt][0], scale, -mn0));
            sacc[nt][1] = __expf(fmaf(sacc[nt][1], scale, -mn0));
            sacc[nt][2] = __expf(fmaf(sacc[nt][2], scale, -mn1));
            sacc[nt][3] = __expf(fmaf(sacc[nt][3], scale, -mn1));
            rs0 += sacc[nt][0] + sacc[nt][1];
            rs1 += sacc[nt][2] + sacc[nt][3];
        }
        rs0 += __shfl_xor_sync(0xffffffffu, rs0, 1);
        rs0 += __shfl_xor_sync(0xffffffffu, rs0, 2);
        rs1 += __shfl_xor_sync(0xffffffffu, rs1, 1);
        rs1 += __shfl_xor_sync(0xffffffffu, rs1, 2);
        l0 = l0 * f0 + rs0;
        l1 = l1 * f1 + rs1;
#pragma unroll
        for (int nt = 0; nt < 8; nt++) {
            O[nt][0] *= f0; O[nt][1] *= f0;
            O[nt][2] *= f1; O[nt][3] *= f1;
        }

        // ---- O += P V (3-term split, term-swept in groups of 4) ----
        const uint32_t VHs = stage + 16384, VLs = stage + 24576;
#pragma unroll
        for (int pk = 0; pk < 4; pk++) {
            uint32_t ph[4], pl[4];
#pragma unroll
            for (int half = 0; half < 2; half++) {
                int nt = 2 * pk + half;
                __nv_bfloat162 a0 = __floats2bfloat162_rn(sacc[nt][0], sacc[nt][1]);
                __nv_bfloat162 a1 = __floats2bfloat162_rn(sacc[nt][2], sacc[nt][3]);
                ph[2*half + 0] = *(uint32_t*)&a0;
                ph[2*half + 1] = *(uint32_t*)&a1;
                __nv_bfloat162 b0 = __floats2bfloat162_rn(
                    sacc[nt][0] - __bfloat162float(a0.x), sacc[nt][1] - __bfloat162float(a0.y));
                __nv_bfloat162 b1 = __floats2bfloat162_rn(
                    sacc[nt][2] - __bfloat162float(a1.x), sacc[nt][3] - __bfloat162float(a1.y));
                pl[2*half + 0] = *(uint32_t*)&b0;
                pl[2*half + 1] = *(uint32_t*)&b1;
            }
            int r = pk * 16 + rV;
#pragma unroll
            for (int g = 0; g < 2; g++) {
                uint32_t vh[4][2], vl[4][2];
#pragma unroll
                for (int j = 0; j < 4; j++) {
                    int nt = g * 4 + j;
                    uint32_t off = (uint32_t)(r * 128 + ((nt ^ (r & 7)) << 4));
                    ldsm_x2t(vh[j][0], vh[j][1], VHs + off);
                    ldsm_x2t(vl[j][0], vl[j][1], VLs + off);
                }
#pragma unroll
                for (int j = 0; j < 4; j++) mma16816(O[g*4+j], ph, vh[j]);
#pragma unroll
                for (int j = 0; j < 4; j++) mma16816(O[g*4+j], ph, vl[j]);
#pragma unroll
                for (int j = 0; j < 4; j++) mma16816(O[g*4+j], pl, vh[j]);
            }
        }
        __syncthreads();
    }

    // ---- epilogue ----
    const float inv0 = 1.0f / l0, inv1 = 1.0f / l1;
    const float omc = 1.0f - cg;
    const int row0 = q0 + wid * 16 + (lane >> 2);
    const int row1 = row0 + 8;
#pragma unroll
    for (int nt = 0; nt < 8; nt++) {
        int dk = nt * 8 + (lane & 3) * 2;
        float vm0 = vmean[bh * DKK + dk], vm1 = vmean[bh * DKK + dk + 1];
        float o00 = cg * O[nt][0] * inv0 + omc * vm0;
        float o01 = cg * O[nt][1] * inv0 + omc * vm1;
        float o10 = cg * O[nt][2] * inv1 + omc * vm0;
        float o11 = cg * O[nt][3] * inv1 + omc * vm1;
        size_t i0 = ((size_t)b * TT + row0) * DD + h * DKK + dk;
        size_t i1 = ((size_t)b * TT + row1) * DD + h * DKK + dk;
        __nv_bfloat162 h0 = __floats2bfloat162_rn(o00, o01);
        __nv_bfloat162 h1 = __floats2bfloat162_rn(o10, o11);
        *(__nv_bfloat162*)(outH + i0) = h0;
        *(__nv_bfloat162*)(outH + i1) = h1;
        *(__nv_bfloat162*)(outL + i0) = __floats2bfloat162_rn(
            o00 - __bfloat162float(h0.x), o01 - __bfloat162float(h0.y));
        *(__nv_bfloat162*)(outL + i1) = __floats2bfloat162_rn(
            o10 - __bfloat162float(h1.x), o11 - __bfloat162float(h1.y));
    }
}

// ---------------------------------------------------------------------------
extern "C" void kernel_launch(void* const* d_in, const int* in_sizes, int n_in,
                              void* d_out, int out_size) {
    const float* x   = (const float*)d_in[0];
    const float* Wq  = (const float*)d_in[1];
    const float* bq  = (const float*)d_in[2];
    const float* Wk  = (const float*)d_in[3];
    const float* bk  = (const float*)d_in[4];
    const float* Wv  = (const float*)d_in[5];
    const float* bv  = (const float*)d_in[6];
    const float* Wo  = (const float*)d_in[7];
    const float* bo  = (const float*)d_in[8];
    const float* Wg1 = (const float*)d_in[9];
    const float* bg1 = (const float*)d_in[10];
    const float* Wg2 = (const float*)d_in[11];
    const float* bg2 = (const float*)d_in[12];
    float* out = (float*)d_out;

    float *pVm, *pC, *pS;
    __nv_bfloat16 *pQh, *pQl, *pKh, *pKl, *pVh, *pVl;
    __nv_bfloat16 *pxh, *pxl, *pWhQ, *pWlQ, *pWhK, *pWlK, *pWhV, *pWlV, *pWhO, *pWlO, *paH, *paL;
    cudaGetSymbolAddress((void**)&pQh, g_Qh);
    cudaGetSymbolAddress((void**)&pQl, g_Ql);
    cudaGetSymbolAddress((void**)&pKh, g_Kh);
    cudaGetSymbolAddress((void**)&pKl, g_Kl);
    cudaGetSymbolAddress((void**)&pVh, g_Vh);
    cudaGetSymbolAddress((void**)&pVl, g_Vl);
    cudaGetSymbolAddress((void**)&pVm, g_vmean);
    cudaGetSymbolAddress((void**)&pC, g_c);
    cudaGetSymbolAddress((void**)&pS, g_scale);
    cudaGetSymbolAddress((void**)&pxh, g_xh);
    cudaGetSymbolAddress((void**)&pxl, g_xl);
    cudaGetSymbolAddress((void**)&pWhQ, g_WhQ);
    cudaGetSymbolAddress((void**)&pWlQ, g_WlQ);
    cudaGetSymbolAddress((void**)&pWhK, g_WhK);
    cudaGetSymbolAddress((void**)&pWlK, g_WlK);
    cudaGetSymbolAddress((void**)&pWhV, g_WhV);
    cudaGetSymbolAddress((void**)&pWlV, g_WlV);
    cudaGetSymbolAddress((void**)&pWhO, g_WhO);
    cudaGetSymbolAddress((void**)&pWlO, g_WlO);
    cudaGetSymbolAddress((void**)&paH, g_aH);
    cudaGetSymbolAddress((void**)&paL, g_aL);

    convert_hl<<<(MROWS*DD/4 + 255)/256, 256>>>(x,  pxh,  pxl,  MROWS*DD/4);
    convert_hl<<<(DD*DD/4 + 255)/256, 256>>>(Wq, pWhQ, pWlQ, DD*DD/4);
    convert_hl<<<(DD*DD/4 + 255)/256, 256>>>(Wk, pWhK, pWlK, DD*DD/4);
    convert_hl<<<(DD*DD/4 + 255)/256, 256>>>(Wv, pWhV, pWlV, DD*DD/4);
    convert_hl<<<(DD*DD/4 + 255)/256, 256>>>(Wo, pWhO, pWlO, DD*DD/4);

    const int GEMM_SMEM = 131072;
    cudaFuncSetAttribute(gemm_mma<1>, cudaFuncAttributeMaxDynamicSharedMemorySize, GEMM_SMEM);
    cudaFuncSetAttribute(gemm_mma<0>, cudaFuncAttributeMaxDynamicSharedMemorySize, GEMM_SMEM);

    GemmArgs qkv = {};
    qkv.Ah = pxh; qkv.Al = pxl;
    qkv.Wh0 = pWhQ; qkv.Wl0 = pWlQ; qkv.Wh1 = pWhK; qkv.Wl1 = pWlK; qkv.Wh2 = pWhV; qkv.Wl2 = pWlV;
    qkv.b0 = bq; qkv.b1 = bk; qkv.b2 = bv;
    qkv.Ch0 = pQh; qkv.Cl0 = pQl; qkv.Ch1 = pKh; qkv.Cl1 = pKl; qkv.Ch2 = pVh; qkv.Cl2 = pVl;
    dim3 qkv_grid(DD/128, MROWS/128, 3);
    gemm_mma<1><<<qkv_grid, 256, GEMM_SMEM>>>(qkv);

    int write_u = (out_size >= BB*TT*DD + BB) ? 1 : 0;
    gate_kernel<<<BB, 256>>>(pQh, pQl, Wg1, bg1, Wg2, bg2, pC, pS,
                             out + (size_t)BB*TT*DD, write_u);
    vmean_kernel<<<BB*HH, 256>>>(pVh, pVl, pVm);

    const int ATTN_SMEM = 32768 + 2 * 32768;   // 98304
    cudaFuncSetAttribute(attn_mma, cudaFuncAttributeMaxDynamicSharedMemorySize, ATTN_SMEM);
    dim3 attn_grid(TT/128, BB*HH);
    attn_mma<<<attn_grid, 256, ATTN_SMEM>>>(pQh, pQl, pKh, pKl, pVh, pVl,
                                            pVm, pC, pS, paH, paL);

    GemmArgs oproj = {};
    oproj.Ah = paH; oproj.Al = paL;
    oproj.Wh0 = pWhO; oproj.Wl0 = pWlO; oproj.Wh1 = pWhO; oproj.Wl1 = pWlO; oproj.Wh2 = pWhO; oproj.Wl2 = pWlO;
    oproj.b0 = bo; oproj.b1 = bo; oproj.b2 = bo;
    oproj.C0 = out;
    dim3 o_grid(DD/128, MROWS/128, 1);
    gemm_mma<0><<<o_grid, 256, GEMM_SMEM>>>(oproj);
}

// round 9
// speedup vs baseline: 1.0890x; 1.0890x over previous
#include <cuda_runtime.h>
#include <cuda_bf16.h>
#include <math.h>
#include <stdint.h>

#define BB 4
#define TT 1024
#define DD 1024
#define HH 16
#define DKK 64
#define MROWS (BB*TT)   // 4096

// ---------------- scratch (static device globals) ----------------
__device__ __nv_bfloat16 g_Qh[BB*HH*TT*DKK], g_Ql[BB*HH*TT*DKK];
__device__ __nv_bfloat16 g_Kh[BB*HH*TT*DKK], g_Kl[BB*HH*TT*DKK];
__device__ __nv_bfloat16 g_Vh[BB*HH*TT*DKK], g_Vl[BB*HH*TT*DKK];
__device__ float g_vmean[BB*HH*DKK];
__device__ float g_c[BB];
__device__ float g_scale[BB];
__device__ __nv_bfloat16 g_xh[MROWS*DD], g_xl[MROWS*DD];
__device__ __nv_bfloat16 g_WhQ[DD*DD], g_WlQ[DD*DD];
__device__ __nv_bfloat16 g_WhK[DD*DD], g_WlK[DD*DD];
__device__ __nv_bfloat16 g_WhV[DD*DD], g_WlV[DD*DD];
__device__ __nv_bfloat16 g_WhO[DD*DD], g_WlO[DD*DD];
__device__ __nv_bfloat16 g_aH[MROWS*DD], g_aL[MROWS*DD];

// ---------------- PTX helpers (sm_80-era only) ----------------
__device__ __forceinline__ uint32_t smem_u32(const void* p) {
    uint32_t a;
    asm("{ .reg .u64 t; cvta.to.shared.u64 t, %1; cvt.u32.u64 %0, t; }" : "=r"(a) : "l"(p));
    return a;
}
#define CP_ASYNC16(dst, src) asm volatile("cp.async.cg.shared.global [%0], [%1], 16;" :: "r"(dst), "l"(src))
#define CP_COMMIT()          asm volatile("cp.async.commit_group;" ::: "memory")
#define CP_WAIT(n)           asm volatile("cp.async.wait_group %0;" :: "n"(n) : "memory")

__device__ __forceinline__ void ldsm_x4(uint32_t& r0, uint32_t& r1, uint32_t& r2, uint32_t& r3, uint32_t addr) {
    asm volatile("ldmatrix.sync.aligned.m8n8.x4.shared.b16 {%0,%1,%2,%3}, [%4];"
                 : "=r"(r0), "=r"(r1), "=r"(r2), "=r"(r3) : "r"(addr));
}
__device__ __forceinline__ void ldsm_x2(uint32_t& r0, uint32_t& r1, uint32_t addr) {
    asm volatile("ldmatrix.sync.aligned.m8n8.x2.shared.b16 {%0,%1}, [%2];"
                 : "=r"(r0), "=r"(r1) : "r"(addr));
}
__device__ __forceinline__ void ldsm_x2t(uint32_t& r0, uint32_t& r1, uint32_t addr) {
    asm volatile("ldmatrix.sync.aligned.m8n8.x2.trans.shared.b16 {%0,%1}, [%2];"
                 : "=r"(r0), "=r"(r1) : "r"(addr));
}
__device__ __forceinline__ void mma16816(float* d, const uint32_t* a, const uint32_t* b) {
    asm volatile("mma.sync.aligned.m16n8k16.row.col.f32.bf16.bf16.f32 "
                 "{%0,%1,%2,%3},{%4,%5,%6,%7},{%8,%9},{%0,%1,%2,%3};"
                 : "+f"(d[0]), "+f"(d[1]), "+f"(d[2]), "+f"(d[3])
                 : "r"(a[0]), "r"(a[1]), "r"(a[2]), "r"(a[3]), "r"(b[0]), "r"(b[1]));
}

// ---------------------------------------------------------------------------
// Split-bf16 warp-MMA GEMM: C[m,n] = sum_k A[m,k]*W[n,k] + bias[n]
// CTA tile 256x128, warp tile 64x64 (8 warps, 4x2), BK=64, 2-stage cp.async.
// MODE 0: C fp32 rowmajor.  MODE 1: split-bf16 hi/lo scatter to [B,H,T,DK].
// Stage layout: Ah@0 (32K), Al@32K, Bh@64K (16K), Bl@80K. Stage = 96K.
// ---------------------------------------------------------------------------
struct GemmArgs {
    const __nv_bfloat16 *Ah, *Al;
    const __nv_bfloat16 *Wh0, *Wl0, *Wh1, *Wl1, *Wh2, *Wl2;
    const float *b0, *b1, *b2;
    float *C0;                                        // MODE 0
    __nv_bfloat16 *Ch0, *Cl0, *Ch1, *Cl1, *Ch2, *Cl2; // MODE 1
};

#define GSTAGE 98304

__device__ __forceinline__ void load_stage(uint32_t sbase, int tid,
                                           const __nv_bfloat16* Ah, const __nv_bfloat16* Al,
                                           const __nv_bfloat16* Wh, const __nv_bfloat16* Wl,
                                           int bm, int bn, int k0) {
#pragma unroll
    for (int i = 0; i < 8; i++) {           // A: 256 rows x 8 chunks
        int g = tid + i * 256;
        int r = g >> 3, c = g & 7;
        uint32_t sw = (uint32_t)(r * 128 + ((c ^ (r & 7)) << 4));
        size_t ga = (size_t)(bm + r) * 1024 + k0;
        CP_ASYNC16(sbase +     0 + sw, (const char*)(Ah + ga) + c * 16);
        CP_ASYNC16(sbase + 32768 + sw, (const char*)(Al + ga) + c * 16);
    }
#pragma unroll
    for (int i = 0; i < 4; i++) {           // B: 128 rows x 8 chunks
        int g = tid + i * 256;
        int r = g >> 3, c = g & 7;
        uint32_t sw = (uint32_t)(r * 128 + ((c ^ (r & 7)) << 4));
        size_t gw = (size_t)(bn + r) * 1024 + k0;
        CP_ASYNC16(sbase + 65536 + sw, (const char*)(Wh + gw) + c * 16);
        CP_ASYNC16(sbase + 81920 + sw, (const char*)(Wl + gw) + c * 16);
    }
}

__device__ __forceinline__ void compute_stage(uint32_t base, int wm, int wn, int lane,
                                              float acc[4][8][4]) {
    const uint32_t aH = base, aL = base + 32768, bH = base + 65536, bL = base + 81920;
    const int rA = wm + (lane & 15);
    const int hA = lane >> 4;
    const int rB = wn + (lane & 7);
    const int hB = (lane >> 3) & 1;
#pragma unroll
    for (int ks = 0; ks < 4; ks++) {
        uint32_t Af[4][4], Alf[4][4], Bf[8][2], Blf[8][2];
#pragma unroll
        for (int mt = 0; mt < 4; mt++) {
            int r = rA + mt * 16;
            uint32_t off = (uint32_t)(r * 128 + (((ks * 2 + hA) ^ (r & 7)) << 4));
            ldsm_x4(Af[mt][0], Af[mt][1], Af[mt][2], Af[mt][3], aH + off);
            ldsm_x4(Alf[mt][0], Alf[mt][1], Alf[mt][2], Alf[mt][3], aL + off);
        }
#pragma unroll
        for (int nt = 0; nt < 8; nt++) {
            int r = rB + nt * 8;
            uint32_t off = (uint32_t)(r * 128 + (((ks * 2 + hB) ^ (r & 7)) << 4));
            ldsm_x2(Bf[nt][0], Bf[nt][1], bH + off);
            ldsm_x2(Blf[nt][0], Blf[nt][1], bL + off);
        }
#pragma unroll
        for (int mt = 0; mt < 4; mt++)
#pragma unroll
            for (int nt = 0; nt < 8; nt++)
                mma16816(acc[mt][nt], Af[mt], Bf[nt]);
#pragma unroll
        for (int mt = 0; mt < 4; mt++)
#pragma unroll
            for (int nt = 0; nt < 8; nt++)
                mma16816(acc[mt][nt], Af[mt], Blf[nt]);
#pragma unroll
        for (int mt = 0; mt < 4; mt++)
#pragma unroll
            for (int nt = 0; nt < 8; nt++)
                mma16816(acc[mt][nt], Alf[mt], Bf[nt]);
    }
}

template<int MODE>
__global__ __launch_bounds__(256)
void gemm_mma(GemmArgs args) {
    extern __shared__ char smem[];
    const int tid = threadIdx.x, wid = tid >> 5, lane = tid & 31;
    const int z = blockIdx.z;
    const __nv_bfloat16* Ah = args.Ah;
    const __nv_bfloat16* Al = args.Al;
    const __nv_bfloat16* Wh = (z == 0) ? args.Wh0 : (z == 1) ? args.Wh1 : args.Wh2;
    const __nv_bfloat16* Wl = (z == 0) ? args.Wl0 : (z == 1) ? args.Wl1 : args.Wl2;
    const float* bias = (z == 0) ? args.b0 : (z == 1) ? args.b1 : args.b2;
    __nv_bfloat16* Ch = (z == 0) ? args.Ch0 : (z == 1) ? args.Ch1 : args.Ch2;
    __nv_bfloat16* Cl = (z == 0) ? args.Cl0 : (z == 1) ? args.Cl1 : args.Cl2;

    const int bm = blockIdx.y * 256, bn = blockIdx.x * 128;
    const int wm = (wid >> 1) * 64, wn = (wid & 1) * 64;
    const uint32_t s0 = smem_u32(smem);

    float acc[4][8][4];
#pragma unroll
    for (int a = 0; a < 4; a++)
#pragma unroll
        for (int b = 0; b < 8; b++)
#pragma unroll
            for (int c = 0; c < 4; c++) acc[a][b][c] = 0.f;

    load_stage(s0, tid, Ah, Al, Wh, Wl, bm, bn, 0);
    CP_COMMIT();

    for (int kt = 0; kt < 16; kt++) {
        if (kt + 1 < 16) {
            load_stage(s0 + ((kt + 1) & 1) * GSTAGE, tid, Ah, Al, Wh, Wl, bm, bn, (kt + 1) * 64);
            CP_COMMIT();
            CP_WAIT(1);
        } else {
            CP_WAIT(0);
        }
        __syncthreads();
        compute_stage(s0 + (kt & 1) * GSTAGE, wm, wn, lane, acc);
        __syncthreads();
    }

    const int lr = lane >> 2, lc = (lane & 3) * 2;
#pragma unroll
    for (int mt = 0; mt < 4; mt++) {
#pragma unroll
        for (int nt = 0; nt < 8; nt++) {
            int c0 = bn + wn + nt * 8 + lc;
            float b0 = __ldg(bias + c0), b1 = __ldg(bias + c0 + 1);
            int r0 = bm + wm + mt * 16 + lr;
            int r1 = r0 + 8;
            float v00 = acc[mt][nt][0] + b0, v01 = acc[mt][nt][1] + b1;
            float v10 = acc[mt][nt][2] + b0, v11 = acc[mt][nt][3] + b1;
            if (MODE == 0) {
                *(float2*)(args.C0 + (size_t)r0 * 1024 + c0) = make_float2(v00, v01);
                *(float2*)(args.C0 + (size_t)r1 * 1024 + c0) = make_float2(v10, v11);
            } else {
                int h = c0 >> 6, dk = c0 & 63;
                size_t i0 = (((size_t)((r0 >> 10) * HH + h)) * TT + (r0 & 1023)) * DKK + dk;
                size_t i1 = (((size_t)((r1 >> 10) * HH + h)) * TT + (r1 & 1023)) * DKK + dk;
                __nv_bfloat162 h0 = __floats2bfloat162_rn(v00, v01);
                __nv_bfloat162 h1 = __floats2bfloat162_rn(v10, v11);
                *(__nv_bfloat162*)(Ch + i0) = h0;
                *(__nv_bfloat162*)(Ch + i1) = h1;
                *(__nv_bfloat162*)(Cl + i0) = __floats2bfloat162_rn(
                    v00 - __bfloat162float(h0.x), v01 - __bfloat162float(h0.y));
                *(__nv_bfloat162*)(Cl + i1) = __floats2bfloat162_rn(
                    v10 - __bfloat162float(h1.x), v11 - __bfloat162float(h1.y));
            }
        }
    }
}

// ---------------------------------------------------------------------------
__device__ __forceinline__ void split_store(const float4 v, __nv_bfloat16* h,
                                            __nv_bfloat16* l, int i) {
    __nv_bfloat16 h0 = __float2bfloat16(v.x);
    __nv_bfloat16 h1 = __float2bfloat16(v.y);
    __nv_bfloat16 h2 = __float2bfloat16(v.z);
    __nv_bfloat16 h3 = __float2bfloat16(v.w);
    __nv_bfloat162 hp0; hp0.x = h0; hp0.y = h1;
    __nv_bfloat162 hp1; hp1.x = h2; hp1.y = h3;
    ((__nv_bfloat162*)h)[i * 2 + 0] = hp0;
    ((__nv_bfloat162*)h)[i * 2 + 1] = hp1;
    __nv_bfloat162 lp0, lp1;
    lp0.x = __float2bfloat16(v.x - __bfloat162float(h0));
    lp0.y = __float2bfloat16(v.y - __bfloat162float(h1));
    lp1.x = __float2bfloat16(v.z - __bfloat162float(h2));
    lp1.y = __float2bfloat16(v.w - __bfloat162float(h3));
    ((__nv_bfloat162*)l)[i * 2 + 0] = lp0;
    ((__nv_bfloat162*)l)[i * 2 + 1] = lp1;
}

__global__ void convert_hl(const float* __restrict__ src,
                           __nv_bfloat16* __restrict__ h,
                           __nv_bfloat16* __restrict__ l, int n4) {
    int i = blockIdx.x * 256 + threadIdx.x;
    if (i >= n4) return;
    split_store(((const float4*)src)[i], h, l, i);
}

struct Cvt4 {
    const float* s[4];
    __nv_bfloat16* h[4];
    __nv_bfloat16* l[4];
};
__global__ void convert_hl4(Cvt4 a, int n4) {
    int w = blockIdx.y;
    int i = blockIdx.x * 256 + threadIdx.x;
    if (i >= n4) return;
    split_store(((const float4*)a.s[w])[i], a.h[w], a.l[w], i);
}

// ---------------------------------------------------------------------------
__global__ void gate_kernel(const __nv_bfloat16* __restrict__ Qh,
                            const __nv_bfloat16* __restrict__ Ql,
                            const float* __restrict__ Wg1, const float* __restrict__ bg1,
                            const float* __restrict__ Wg2, const float* __restrict__ bg2,
                            float* __restrict__ c_out, float* __restrict__ scale_out,
                            float* __restrict__ u_out, int write_u) {
    int b = blockIdx.x;
    float s1 = 0.f, s2 = 0.f;
    for (int d = threadIdx.x; d < DD; d += 256) {
        size_t idx = ((size_t)(b*HH + (d >> 6)))*TT*DKK + (d & 63);
        float q = __bfloat162float(Qh[idx]) + __bfloat162float(Ql[idx]);
        s1 += q * Wg1[d];
        s2 += q * Wg2[d];
    }
#pragma unroll
    for (int off = 16; off >= 1; off >>= 1) {
        s1 += __shfl_xor_sync(0xffffffffu, s1, off);
        s2 += __shfl_xor_sync(0xffffffffu, s2, off);
    }
    __shared__ float r1[8], r2[8];
    int lane = threadIdx.x & 31, w = threadIdx.x >> 5;
    if (lane == 0) { r1[w] = s1; r2[w] = s2; }
    __syncthreads();
    if (threadIdx.x == 0) {
        float t1 = 0.f, t2 = 0.f;
        for (int i = 0; i < 8; i++) { t1 += r1[i]; t2 += r2[i]; }
        float z1 = t1 + bg1[0], z2 = t2 + bg2[0];
        float q1 = 1.f / (1.f + expf(-z1));
        float q2 = 1.f / (1.f + expf(-z2));
        float c = fminf(fmaxf(q1 * q2, 1e-8f), 1.0f);
        float tau = (c < 0.3f) ? (1.0f / c) : 1.0f;
        c_out[b] = c;
        scale_out[b] = 1.0f / (8.0f * tau);
        if (write_u) u_out[b] = 1.0f - c;
    }
}

// ---------------------------------------------------------------------------
__global__ void vmean_kernel(const __nv_bfloat16* __restrict__ Vh,
                             const __nv_bfloat16* __restrict__ Vl,
                             float* __restrict__ vmean) {
    __shared__ float sm[256];
    int bh = blockIdx.x, tid = threadIdx.x;
    int dk = tid & 63, part = tid >> 6;
    size_t base = (size_t)bh * TT * DKK;
    float s = 0.f;
    for (int t = part; t < TT; t += 4) {
        size_t i = base + (size_t)t * DKK + dk;
        s += __bfloat162float(Vh[i]) + __bfloat162float(Vl[i]);
    }
    sm[tid] = s;
    __syncthreads();
    if (part == 0)
        vmean[bh*DKK + dk] = (sm[dk] + sm[64+dk] + sm[128+dk] + sm[192+dk]) * (1.0f/1024.0f);
}

// ---------------------------------------------------------------------------
// Tensor-core flash attention. Block = 256 queries x (b,h). 8 warps x 32 rows
// (2 row-tiles each) -> K/V fragment loads amortized over 2x the MMAs.
// SMEM: Qh@0 (32K), Ql@32K; stages @64K: {Kh,Kl,Vh,Vl} 8K each, 32K/stage x2.
// ---------------------------------------------------------------------------
__global__ __launch_bounds__(256)
void attn_mma(const __nv_bfloat16* __restrict__ Qh, const __nv_bfloat16* __restrict__ Ql,
              const __nv_bfloat16* __restrict__ Kh, const __nv_bfloat16* __restrict__ Kl,
              const __nv_bfloat16* __restrict__ Vh, const __nv_bfloat16* __restrict__ Vl,
              const float* __restrict__ vmean,
              const float* __restrict__ c_arr, const float* __restrict__ scale_arr,
              __nv_bfloat16* __restrict__ outH, __nv_bfloat16* __restrict__ outL) {
    extern __shared__ char smem[];
    const int tid = threadIdx.x, wid = tid >> 5, lane = tid & 31;
    const int bh = blockIdx.y;
    const int b = bh >> 4, h = bh & 15;
    const int q0 = blockIdx.x * 256;
    const float scale = scale_arr[b];
    const float cg = c_arr[b];
    const size_t gbase = (size_t)bh * TT * DKK;

    const uint32_t s0 = smem_u32(smem);
    const uint32_t QH = s0, QL = s0 + 32768;
    const uint32_t ST = s0 + 65536;

    // Q tile: 2 arrays x 256 rows x 8 chunks = 4096 chunks, 16 iters
#pragma unroll
    for (int i = 0; i < 16; i++) {
        int g = tid + i * 256;
        int arr = g >> 11;
        int rem = g & 2047;
        int r = rem >> 3, c = rem & 7;
        uint32_t sw = (uint32_t)(r * 128 + ((c ^ (r & 7)) << 4));
        const __nv_bfloat16* src = arr ? Ql : Qh;
        CP_ASYNC16((arr ? QL : QH) + sw, (const char*)(src + gbase + (size_t)(q0 + r) * 64) + c * 16);
    }
    // KV stage 0: 4 arrays x 64 rows x 8 chunks = 2048 chunks, 8 iters
#pragma unroll
    for (int i = 0; i < 8; i++) {
        int g = tid + i * 256;
        int arr = g >> 9;
        int rem = g & 511;
        int r = rem >> 3, c = rem & 7;
        uint32_t sw = (uint32_t)(r * 128 + ((c ^ (r & 7)) << 4));
        const __nv_bfloat16* src = (arr == 0) ? Kh : (arr == 1) ? Kl : (arr == 2) ? Vh : Vl;
        CP_ASYNC16(ST + arr * 8192 + sw, (const char*)(src + gbase + (size_t)r * 64) + c * 16);
    }
    CP_COMMIT();

    const int hA = lane >> 4;
    const int rB = lane & 7;
    const int hB = (lane >> 3) & 1;
    const int rV = lane & 15;

    uint32_t qhF[2][4][4], qlF[2][4][4];
    float O[2][8][4];
    float mcur[2][2], lsum[2][2];
#pragma unroll
    for (int mt = 0; mt < 2; mt++) {
        mcur[mt][0] = -1e30f; mcur[mt][1] = -1e30f;
        lsum[mt][0] = 0.f;    lsum[mt][1] = 0.f;
#pragma unroll
        for (int nt = 0; nt < 8; nt++)
#pragma unroll
            for (int j = 0; j < 4; j++) O[mt][nt][j] = 0.f;
    }

    for (int kt = 0; kt < 16; kt++) {
        const uint32_t stage = ST + (kt & 1) * 32768;
        if (kt + 1 < 16) {
            const uint32_t nstage = ST + ((kt + 1) & 1) * 32768;
            const int k0n = (kt + 1) * 64;
#pragma unroll
            for (int i = 0; i < 8; i++) {
                int g = tid + i * 256;
                int arr = g >> 9;
                int rem = g & 511;
                int r = rem >> 3, c = rem & 7;
                uint32_t sw = (uint32_t)(r * 128 + ((c ^ (r & 7)) << 4));
                const __nv_bfloat16* src = (arr == 0) ? Kh : (arr == 1) ? Kl : (arr == 2) ? Vh : Vl;
                CP_ASYNC16(nstage + arr * 8192 + sw,
                           (const char*)(src + gbase + (size_t)(k0n + r) * 64) + c * 16);
            }
            CP_COMMIT();
            CP_WAIT(1);
        } else {
            CP_WAIT(0);
        }
        __syncthreads();

        if (kt == 0) {
#pragma unroll
            for (int mt = 0; mt < 2; mt++) {
                int rA = wid * 32 + mt * 16 + (lane & 15);
#pragma unroll
                for (int ks = 0; ks < 4; ks++) {
                    uint32_t off = (uint32_t)(rA * 128 + (((ks * 2 + hA) ^ (rA & 7)) << 4));
                    ldsm_x4(qhF[mt][ks][0], qhF[mt][ks][1], qhF[mt][ks][2], qhF[mt][ks][3], QH + off);
                    ldsm_x4(qlF[mt][ks][0], qlF[mt][ks][1], qlF[mt][ks][2], qlF[mt][ks][3], QL + off);
                }
            }
        }

        // ---- S = Q K^T (3-term split); K frags shared across both row-tiles ----
        float sacc[2][8][4];
#pragma unroll
        for (int mt = 0; mt < 2; mt++)
#pragma unroll
            for (int nt = 0; nt < 8; nt++)
#pragma unroll
                for (int j = 0; j < 4; j++) sacc[mt][nt][j] = 0.f;

        const uint32_t KHs = stage, KLs = stage + 8192;
#pragma unroll
        for (int ks = 0; ks < 4; ks++) {
            uint32_t kh[8][2], kl[8][2];
#pragma unroll
            for (int nt = 0; nt < 8; nt++) {
                int r = nt * 8 + rB;
                uint32_t off = (uint32_t)(r * 128 + (((ks * 2 + hB) ^ (r & 7)) << 4));
                ldsm_x2(kh[nt][0], kh[nt][1], KHs + off);
                ldsm_x2(kl[nt][0], kl[nt][1], KLs + off);
            }
#pragma unroll
            for (int mt = 0; mt < 2; mt++)
#pragma unroll
                for (int nt = 0; nt < 8; nt++)
                    mma16816(sacc[mt][nt], qhF[mt][ks], kh[nt]);
#pragma unroll
            for (int mt = 0; mt < 2; mt++)
#pragma unroll
                for (int nt = 0; nt < 8; nt++)
                    mma16816(sacc[mt][nt], qhF[mt][ks], kl[nt]);
#pragma unroll
            for (int mt = 0; mt < 2; mt++)
#pragma unroll
                for (int nt = 0; nt < 8; nt++)
                    mma16816(sacc[mt][nt], qlF[mt][ks], kh[nt]);
        }

        // ---- online softmax per row-tile ----
        float f[2][2];
#pragma unroll
        for (int mt = 0; mt < 2; mt++) {
            float mx0 = -1e30f, mx1 = -1e30f;
#pragma unroll
            for (int nt = 0; nt < 8; nt++) {
                mx0 = fmaxf(mx0, fmaxf(sacc[mt][nt][0], sacc[mt][nt][1]));
                mx1 = fmaxf(mx1, fmaxf(sacc[mt][nt][2], sacc[mt][nt][3]));
            }
            mx0 = fmaxf(mx0, __shfl_xor_sync(0xffffffffu, mx0, 1));
            mx0 = fmaxf(mx0, __shfl_xor_sync(0xffffffffu, mx0, 2));
            mx1 = fmaxf(mx1, __shfl_xor_sync(0xffffffffu, mx1, 1));
            mx1 = fmaxf(mx1, __shfl_xor_sync(0xffffffffu, mx1, 2));
            float mn0 = fmaxf(mcur[mt][0], mx0 * scale);
            float mn1 = fmaxf(mcur[mt][1], mx1 * scale);
            f[mt][0] = __expf(mcur[mt][0] - mn0);
            f[mt][1] = __expf(mcur[mt][1] - mn1);
            mcur[mt][0] = mn0; mcur[mt][1] = mn1;

            float rs0 = 0.f, rs1 = 0.f;
#pragma unroll
            for (int nt = 0; nt < 8; nt++) {
                sacc[mt][nt][0] = __expf(fmaf(sacc[mt][nt][0], scale, -mn0));
                sacc[mt][nt][1] = __expf(fmaf(sacc[mt][nt][1], scale, -mn0));
                sacc[mt][nt][2] = __expf(fmaf(sacc[mt][nt][2], scale, -mn1));
                sacc[mt][nt][3] = __expf(fmaf(sacc[mt][nt][3], scale, -mn1));
                rs0 += sacc[mt][nt][0] + sacc[mt][nt][1];
                rs1 += sacc[mt][nt][2] + sacc[mt][nt][3];
            }
            rs0 += __shfl_xor_sync(0xffffffffu, rs0, 1);
            rs0 += __shfl_xor_sync(0xffffffffu, rs0, 2);
            rs1 += __shfl_xor_sync(0xffffffffu, rs1, 1);
            rs1 += __shfl_xor_sync(0xffffffffu, rs1, 2);
            lsum[mt][0] = lsum[mt][0] * f[mt][0] + rs0;
            lsum[mt][1] = lsum[mt][1] * f[mt][1] + rs1;
#pragma unroll
            for (int nt = 0; nt < 8; nt++) {
                O[mt][nt][0] *= f[mt][0]; O[mt][nt][1] *= f[mt][0];
                O[mt][nt][2] *= f[mt][1]; O[mt][nt][3] *= f[mt][1];
            }
        }

        // ---- O += P V (3-term split); V frags shared across both row-tiles ----
        const uint32_t VHs = stage + 16384, VLs = stage + 24576;
#pragma unroll
        for (int pk = 0; pk < 4; pk++) {
            uint32_t ph[2][4], pl[2][4];
#pragma unroll
            for (int mt = 0; mt < 2; mt++) {
#pragma unroll
                for (int half = 0; half < 2; half++) {
                    int nt = 2 * pk + half;
                    __nv_bfloat162 a0 = __floats2bfloat162_rn(sacc[mt][nt][0], sacc[mt][nt][1]);
                    __nv_bfloat162 a1 = __floats2bfloat162_rn(sacc[mt][nt][2], sacc[mt][nt][3]);
                    ph[mt][2*half + 0] = *(uint32_t*)&a0;
                    ph[mt][2*half + 1] = *(uint32_t*)&a1;
                    __nv_bfloat162 b0 = __floats2bfloat162_rn(
                        sacc[mt][nt][0] - __bfloat162float(a0.x), sacc[mt][nt][1] - __bfloat162float(a0.y));
                    __nv_bfloat162 b1 = __floats2bfloat162_rn(
                        sacc[mt][nt][2] - __bfloat162float(a1.x), sacc[mt][nt][3] - __bfloat162float(a1.y));
                    pl[mt][2*half + 0] = *(uint32_t*)&b0;
                    pl[mt][2*half + 1] = *(uint32_t*)&b1;
                }
            }
            int r = pk * 16 + rV;
            uint32_t vh[8][2], vl[8][2];
#pragma unroll
            for (int nt = 0; nt < 8; nt++) {
                uint32_t off = (uint32_t)(r * 128 + ((nt ^ (r & 7)) << 4));
                ldsm_x2t(vh[nt][0], vh[nt][1], VHs + off);
                ldsm_x2t(vl[nt][0], vl[nt][1], VLs + off);
            }
#pragma unroll
            for (int mt = 0; mt < 2; mt++)
#pragma unroll
                for (int nt = 0; nt < 8; nt++)
                    mma16816(O[mt][nt], ph[mt], vh[nt]);
#pragma unroll
            for (int mt = 0; mt < 2; mt++)
#pragma unroll
                for (int nt = 0; nt < 8; nt++)
                    mma16816(O[mt][nt], ph[mt], vl[nt]);
#pragma unroll
            for (int mt = 0; mt < 2; mt++)
#pragma unroll
                for (int nt = 0; nt < 8; nt++)
                    mma16816(O[mt][nt], pl[mt], vh[nt]);
        }
        __syncthreads();
    }

    // ---- epilogue ----
    const float omc = 1.0f - cg;
#pragma unroll
    for (int mt = 0; mt < 2; mt++) {
        const float inv0 = 1.0f / lsum[mt][0], inv1 = 1.0f / lsum[mt][1];
        const int row0 = q0 + wid * 32 + mt * 16 + (lane >> 2);
        const int row1 = row0 + 8;
#pragma unroll
        for (int nt = 0; nt < 8; nt++) {
            int dk = nt * 8 + (lane & 3) * 2;
            float vm0 = vmean[bh * DKK + dk], vm1 = vmean[bh * DKK + dk + 1];
            float o00 = cg * O[mt][nt][0] * inv0 + omc * vm0;
            float o01 = cg * O[mt][nt][1] * inv0 + omc * vm1;
            float o10 = cg * O[mt][nt][2] * inv1 + omc * vm0;
            float o11 = cg * O[mt][nt][3] * inv1 + omc * vm1;
            size_t i0 = ((size_t)b * TT + row0) * DD + h * DKK + dk;
            size_t i1 = ((size_t)b * TT + row1) * DD + h * DKK + dk;
            __nv_bfloat162 h0 = __floats2bfloat162_rn(o00, o01);
            __nv_bfloat162 h1 = __floats2bfloat162_rn(o10, o11);
            *(__nv_bfloat162*)(outH + i0) = h0;
            *(__nv_bfloat162*)(outH + i1) = h1;
            *(__nv_bfloat162*)(outL + i0) = __floats2bfloat162_rn(
                o00 - __bfloat162float(h0.x), o01 - __bfloat162float(h0.y));
            *(__nv_bfloat162*)(outL + i1) = __floats2bfloat162_rn(
                o10 - __bfloat162float(h1.x), o11 - __bfloat162float(h1.y));
        }
    }
}

// ---------------------------------------------------------------------------
extern "C" void kernel_launch(void* const* d_in, const int* in_sizes, int n_in,
                              void* d_out, int out_size) {
    const float* x   = (const float*)d_in[0];
    const float* Wq  = (const float*)d_in[1];
    const float* bq  = (const float*)d_in[2];
    const float* Wk  = (const float*)d_in[3];
    const float* bk  = (const float*)d_in[4];
    const float* Wv  = (const float*)d_in[5];
    const float* bv  = (const float*)d_in[6];
    const float* Wo  = (const float*)d_in[7];
    const float* bo  = (const float*)d_in[8];
    const float* Wg1 = (const float*)d_in[9];
    const float* bg1 = (const float*)d_in[10];
    const float* Wg2 = (const float*)d_in[11];
    const float* bg2 = (const float*)d_in[12];
    float* out = (float*)d_out;

    float *pVm, *pC, *pS;
    __nv_bfloat16 *pQh, *pQl, *pKh, *pKl, *pVh, *pVl;
    __nv_bfloat16 *pxh, *pxl, *pWhQ, *pWlQ, *pWhK, *pWlK, *pWhV, *pWlV, *pWhO, *pWlO, *paH, *paL;
    cudaGetSymbolAddress((void**)&pQh, g_Qh);
    cudaGetSymbolAddress((void**)&pQl, g_Ql);
    cudaGetSymbolAddress((void**)&pKh, g_Kh);
    cudaGetSymbolAddress((void**)&pKl, g_Kl);
    cudaGetSymbolAddress((void**)&pVh, g_Vh);
    cudaGetSymbolAddress((void**)&pVl, g_Vl);
    cudaGetSymbolAddress((void**)&pVm, g_vmean);
    cudaGetSymbolAddress((void**)&pC, g_c);
    cudaGetSymbolAddress((void**)&pS, g_scale);
    cudaGetSymbolAddress((void**)&pxh, g_xh);
    cudaGetSymbolAddress((void**)&pxl, g_xl);
    cudaGetSymbolAddress((void**)&pWhQ, g_WhQ);
    cudaGetSymbolAddress((void**)&pWlQ, g_WlQ);
    cudaGetSymbolAddress((void**)&pWhK, g_WhK);
    cudaGetSymbolAddress((void**)&pWlK, g_WlK);
    cudaGetSymbolAddress((void**)&pWhV, g_WhV);
    cudaGetSymbolAddress((void**)&pWlV, g_WlV);
    cudaGetSymbolAddress((void**)&pWhO, g_WhO);
    cudaGetSymbolAddress((void**)&pWlO, g_WlO);
    cudaGetSymbolAddress((void**)&paH, g_aH);
    cudaGetSymbolAddress((void**)&paL, g_aL);

    convert_hl<<<(MROWS*DD/4 + 255)/256, 256>>>(x, pxh, pxl, MROWS*DD/4);
    Cvt4 cw;
    cw.s[0] = Wq; cw.h[0] = pWhQ; cw.l[0] = pWlQ;
    cw.s[1] = Wk; cw.h[1] = pWhK; cw.l[1] = pWlK;
    cw.s[2] = Wv; cw.h[2] = pWhV; cw.l[2] = pWlV;
    cw.s[3] = Wo; cw.h[3] = pWhO; cw.l[3] = pWlO;
    dim3 cvt_grid((DD*DD/4 + 255)/256, 4);
    convert_hl4<<<cvt_grid, 256>>>(cw, DD*DD/4);

    const int GEMM_SMEM = 2 * GSTAGE;   // 196608
    cudaFuncSetAttribute(gemm_mma<1>, cudaFuncAttributeMaxDynamicSharedMemorySize, GEMM_SMEM);
    cudaFuncSetAttribute(gemm_mma<0>, cudaFuncAttributeMaxDynamicSharedMemorySize, GEMM_SMEM);

    GemmArgs qkv = {};
    qkv.Ah = pxh; qkv.Al = pxl;
    qkv.Wh0 = pWhQ; qkv.Wl0 = pWlQ; qkv.Wh1 = pWhK; qkv.Wl1 = pWlK; qkv.Wh2 = pWhV; qkv.Wl2 = pWlV;
    qkv.b0 = bq; qkv.b1 = bk; qkv.b2 = bv;
    qkv.Ch0 = pQh; qkv.Cl0 = pQl; qkv.Ch1 = pKh; qkv.Cl1 = pKl; qkv.Ch2 = pVh; qkv.Cl2 = pVl;
    dim3 qkv_grid(DD/128, MROWS/256, 3);        // (8, 16, 3)
    gemm_mma<1><<<qkv_grid, 256, GEMM_SMEM>>>(qkv);

    int write_u = (out_size >= BB*TT*DD + BB) ? 1 : 0;
    gate_kernel<<<BB, 256>>>(pQh, pQl, Wg1, bg1, Wg2, bg2, pC, pS,
                             out + (size_t)BB*TT*DD, write_u);
    vmean_kernel<<<BB*HH, 256>>>(pVh, pVl, pVm);

    const int ATTN_SMEM = 65536 + 2 * 32768;    // 131072
    cudaFuncSetAttribute(attn_mma, cudaFuncAttributeMaxDynamicSharedMemorySize, ATTN_SMEM);
    dim3 attn_grid(TT/256, BB*HH);              // (4, 64)
    attn_mma<<<attn_grid, 256, ATTN_SMEM>>>(pQh, pQl, pKh, pKl, pVh, pVl,
                                            pVm, pC, pS, paH, paL);

    GemmArgs oproj = {};
    oproj.Ah = paH; oproj.Al = paL;
    oproj.Wh0 = pWhO; oproj.Wl0 = pWlO; oproj.Wh1 = pWhO; oproj.Wl1 = pWlO; oproj.Wh2 = pWhO; oproj.Wl2 = pWlO;
    oproj.b0 = bo; oproj.b1 = bo; oproj.b2 = bo;
    oproj.C0 = out;
    dim3 o_grid(DD/128, MROWS/256, 1);          // (8, 16, 1)
    gemm_mma<0><<<o_grid, 256, GEMM_SMEM>>>(oproj);
}

// round 10
// speedup vs baseline: 1.1010x; 1.0110x over previous
#include <cuda_runtime.h>
#include <cuda_bf16.h>
#include <math.h>
#include <stdint.h>

#define BB 4
#define TT 1024
#define DD 1024
#define HH 16
#define DKK 64
#define MROWS (BB*TT)   // 4096

// ---------------- scratch (static device globals) ----------------
__device__ __nv_bfloat16 g_Qh[BB*HH*TT*DKK], g_Ql[BB*HH*TT*DKK];
__device__ __nv_bfloat16 g_Kh[BB*HH*TT*DKK], g_Kl[BB*HH*TT*DKK];
__device__ __nv_bfloat16 g_Vh[BB*HH*TT*DKK], g_Vl[BB*HH*TT*DKK];
__device__ float g_vmean[BB*HH*DKK];
__device__ float g_c[BB];
__device__ float g_scale[BB];
__device__ __nv_bfloat16 g_xh[MROWS*DD], g_xl[MROWS*DD];
__device__ __nv_bfloat16 g_WhQ[DD*DD], g_WlQ[DD*DD];
__device__ __nv_bfloat16 g_WhK[DD*DD], g_WlK[DD*DD];
__device__ __nv_bfloat16 g_WhV[DD*DD], g_WlV[DD*DD];
__device__ __nv_bfloat16 g_WhO[DD*DD], g_WlO[DD*DD];
__device__ __nv_bfloat16 g_aH[MROWS*DD], g_aL[MROWS*DD];

// ---------------- PTX helpers (sm_80-era only) ----------------
__device__ __forceinline__ uint32_t smem_u32(const void* p) {
    uint32_t a;
    asm("{ .reg .u64 t; cvta.to.shared.u64 t, %1; cvt.u32.u64 %0, t; }" : "=r"(a) : "l"(p));
    return a;
}
#define CP_ASYNC16(dst, src) asm volatile("cp.async.cg.shared.global [%0], [%1], 16;" :: "r"(dst), "l"(src))
#define CP_COMMIT()          asm volatile("cp.async.commit_group;" ::: "memory")
#define CP_WAIT(n)           asm volatile("cp.async.wait_group %0;" :: "n"(n) : "memory")

__device__ __forceinline__ void ldsm_x4(uint32_t& r0, uint32_t& r1, uint32_t& r2, uint32_t& r3, uint32_t addr) {
    asm volatile("ldmatrix.sync.aligned.m8n8.x4.shared.b16 {%0,%1,%2,%3}, [%4];"
                 : "=r"(r0), "=r"(r1), "=r"(r2), "=r"(r3) : "r"(addr));
}
__device__ __forceinline__ void ldsm_x2(uint32_t& r0, uint32_t& r1, uint32_t addr) {
    asm volatile("ldmatrix.sync.aligned.m8n8.x2.shared.b16 {%0,%1}, [%2];"
                 : "=r"(r0), "=r"(r1) : "r"(addr));
}
__device__ __forceinline__ void ldsm_x2t(uint32_t& r0, uint32_t& r1, uint32_t addr) {
    asm volatile("ldmatrix.sync.aligned.m8n8.x2.trans.shared.b16 {%0,%1}, [%2];"
                 : "=r"(r0), "=r"(r1) : "r"(addr));
}
__device__ __forceinline__ void mma16816(float* d, const uint32_t* a, const uint32_t* b) {
    asm volatile("mma.sync.aligned.m16n8k16.row.col.f32.bf16.bf16.f32 "
                 "{%0,%1,%2,%3},{%4,%5,%6,%7},{%8,%9},{%0,%1,%2,%3};"
                 : "+f"(d[0]), "+f"(d[1]), "+f"(d[2]), "+f"(d[3])
                 : "r"(a[0]), "r"(a[1]), "r"(a[2]), "r"(a[3]), "r"(b[0]), "r"(b[1]));
}

// ---------------------------------------------------------------------------
// Split-bf16 warp-MMA GEMM (R9 config): CTA 256x128, warp 64x64, BK=64.
// ---------------------------------------------------------------------------
struct GemmArgs {
    const __nv_bfloat16 *Ah, *Al;
    const __nv_bfloat16 *Wh0, *Wl0, *Wh1, *Wl1, *Wh2, *Wl2;
    const float *b0, *b1, *b2;
    float *C0;                                        // MODE 0
    __nv_bfloat16 *Ch0, *Cl0, *Ch1, *Cl1, *Ch2, *Cl2; // MODE 1
};

#define GSTAGE 98304

__device__ __forceinline__ void load_stage(uint32_t sbase, int tid,
                                           const __nv_bfloat16* Ah, const __nv_bfloat16* Al,
                                           const __nv_bfloat16* Wh, const __nv_bfloat16* Wl,
                                           int bm, int bn, int k0) {
#pragma unroll
    for (int i = 0; i < 8; i++) {
        int g = tid + i * 256;
        int r = g >> 3, c = g & 7;
        uint32_t sw = (uint32_t)(r * 128 + ((c ^ (r & 7)) << 4));
        size_t ga = (size_t)(bm + r) * 1024 + k0;
        CP_ASYNC16(sbase +     0 + sw, (const char*)(Ah + ga) + c * 16);
        CP_ASYNC16(sbase + 32768 + sw, (const char*)(Al + ga) + c * 16);
    }
#pragma unroll
    for (int i = 0; i < 4; i++) {
        int g = tid + i * 256;
        int r = g >> 3, c = g & 7;
        uint32_t sw = (uint32_t)(r * 128 + ((c ^ (r & 7)) << 4));
        size_t gw = (size_t)(bn + r) * 1024 + k0;
        CP_ASYNC16(sbase + 65536 + sw, (const char*)(Wh + gw) + c * 16);
        CP_ASYNC16(sbase + 81920 + sw, (const char*)(Wl + gw) + c * 16);
    }
}

__device__ __forceinline__ void compute_stage(uint32_t base, int wm, int wn, int lane,
                                              float acc[4][8][4]) {
    const uint32_t aH = base, aL = base + 32768, bH = base + 65536, bL = base + 81920;
    const int rA = wm + (lane & 15);
    const int hA = lane >> 4;
    const int rB = wn + (lane & 7);
    const int hB = (lane >> 3) & 1;
#pragma unroll
    for (int ks = 0; ks < 4; ks++) {
        uint32_t Af[4][4], Alf[4][4], Bf[8][2], Blf[8][2];
#pragma unroll
        for (int mt = 0; mt < 4; mt++) {
            int r = rA + mt * 16;
            uint32_t off = (uint32_t)(r * 128 + (((ks * 2 + hA) ^ (r & 7)) << 4));
            ldsm_x4(Af[mt][0], Af[mt][1], Af[mt][2], Af[mt][3], aH + off);
            ldsm_x4(Alf[mt][0], Alf[mt][1], Alf[mt][2], Alf[mt][3], aL + off);
        }
#pragma unroll
        for (int nt = 0; nt < 8; nt++) {
            int r = rB + nt * 8;
            uint32_t off = (uint32_t)(r * 128 + (((ks * 2 + hB) ^ (r & 7)) << 4));
            ldsm_x2(Bf[nt][0], Bf[nt][1], bH + off);
            ldsm_x2(Blf[nt][0], Blf[nt][1], bL + off);
        }
#pragma unroll
        for (int mt = 0; mt < 4; mt++)
#pragma unroll
            for (int nt = 0; nt < 8; nt++)
                mma16816(acc[mt][nt], Af[mt], Bf[nt]);
#pragma unroll
        for (int mt = 0; mt < 4; mt++)
#pragma unroll
            for (int nt = 0; nt < 8; nt++)
                mma16816(acc[mt][nt], Af[mt], Blf[nt]);
#pragma unroll
        for (int mt = 0; mt < 4; mt++)
#pragma unroll
            for (int nt = 0; nt < 8; nt++)
                mma16816(acc[mt][nt], Alf[mt], Bf[nt]);
    }
}

template<int MODE>
__global__ __launch_bounds__(256)
void gemm_mma(GemmArgs args) {
    extern __shared__ char smem[];
    const int tid = threadIdx.x, wid = tid >> 5, lane = tid & 31;
    const int z = blockIdx.z;
    const __nv_bfloat16* Ah = args.Ah;
    const __nv_bfloat16* Al = args.Al;
    const __nv_bfloat16* Wh = (z == 0) ? args.Wh0 : (z == 1) ? args.Wh1 : args.Wh2;
    const __nv_bfloat16* Wl = (z == 0) ? args.Wl0 : (z == 1) ? args.Wl1 : args.Wl2;
    const float* bias = (z == 0) ? args.b0 : (z == 1) ? args.b1 : args.b2;
    __nv_bfloat16* Ch = (z == 0) ? args.Ch0 : (z == 1) ? args.Ch1 : args.Ch2;
    __nv_bfloat16* Cl = (z == 0) ? args.Cl0 : (z == 1) ? args.Cl1 : args.Cl2;

    const int bm = blockIdx.y * 256, bn = blockIdx.x * 128;
    const int wm = (wid >> 1) * 64, wn = (wid & 1) * 64;
    const uint32_t s0 = smem_u32(smem);

    float acc[4][8][4];
#pragma unroll
    for (int a = 0; a < 4; a++)
#pragma unroll
        for (int b = 0; b < 8; b++)
#pragma unroll
            for (int c = 0; c < 4; c++) acc[a][b][c] = 0.f;

    load_stage(s0, tid, Ah, Al, Wh, Wl, bm, bn, 0);
    CP_COMMIT();

    for (int kt = 0; kt < 16; kt++) {
        if (kt + 1 < 16) {
            load_stage(s0 + ((kt + 1) & 1) * GSTAGE, tid, Ah, Al, Wh, Wl, bm, bn, (kt + 1) * 64);
            CP_COMMIT();
            CP_WAIT(1);
        } else {
            CP_WAIT(0);
        }
        __syncthreads();
        compute_stage(s0 + (kt & 1) * GSTAGE, wm, wn, lane, acc);
        __syncthreads();
    }

    const int lr = lane >> 2, lc = (lane & 3) * 2;
#pragma unroll
    for (int mt = 0; mt < 4; mt++) {
#pragma unroll
        for (int nt = 0; nt < 8; nt++) {
            int c0 = bn + wn + nt * 8 + lc;
            float b0 = __ldg(bias + c0), b1 = __ldg(bias + c0 + 1);
            int r0 = bm + wm + mt * 16 + lr;
            int r1 = r0 + 8;
            float v00 = acc[mt][nt][0] + b0, v01 = acc[mt][nt][1] + b1;
            float v10 = acc[mt][nt][2] + b0, v11 = acc[mt][nt][3] + b1;
            if (MODE == 0) {
                *(float2*)(args.C0 + (size_t)r0 * 1024 + c0) = make_float2(v00, v01);
                *(float2*)(args.C0 + (size_t)r1 * 1024 + c0) = make_float2(v10, v11);
            } else {
                int h = c0 >> 6, dk = c0 & 63;
                size_t i0 = (((size_t)((r0 >> 10) * HH + h)) * TT + (r0 & 1023)) * DKK + dk;
                size_t i1 = (((size_t)((r1 >> 10) * HH + h)) * TT + (r1 & 1023)) * DKK + dk;
                __nv_bfloat162 h0 = __floats2bfloat162_rn(v00, v01);
                __nv_bfloat162 h1 = __floats2bfloat162_rn(v10, v11);
                *(__nv_bfloat162*)(Ch + i0) = h0;
                *(__nv_bfloat162*)(Ch + i1) = h1;
                *(__nv_bfloat162*)(Cl + i0) = __floats2bfloat162_rn(
                    v00 - __bfloat162float(h0.x), v01 - __bfloat162float(h0.y));
                *(__nv_bfloat162*)(Cl + i1) = __floats2bfloat162_rn(
                    v10 - __bfloat162float(h1.x), v11 - __bfloat162float(h1.y));
            }
        }
    }
}

// ---------------------------------------------------------------------------
__device__ __forceinline__ void split_store(const float4 v, __nv_bfloat16* h,
                                            __nv_bfloat16* l, int i) {
    __nv_bfloat16 h0 = __float2bfloat16(v.x);
    __nv_bfloat16 h1 = __float2bfloat16(v.y);
    __nv_bfloat16 h2 = __float2bfloat16(v.z);
    __nv_bfloat16 h3 = __float2bfloat16(v.w);
    __nv_bfloat162 hp0; hp0.x = h0; hp0.y = h1;
    __nv_bfloat162 hp1; hp1.x = h2; hp1.y = h3;
    ((__nv_bfloat162*)h)[i * 2 + 0] = hp0;
    ((__nv_bfloat162*)h)[i * 2 + 1] = hp1;
    __nv_bfloat162 lp0, lp1;
    lp0.x = __float2bfloat16(v.x - __bfloat162float(h0));
    lp0.y = __float2bfloat16(v.y - __bfloat162float(h1));
    lp1.x = __float2bfloat16(v.z - __bfloat162float(h2));
    lp1.y = __float2bfloat16(v.w - __bfloat162float(h3));
    ((__nv_bfloat162*)l)[i * 2 + 0] = lp0;
    ((__nv_bfloat162*)l)[i * 2 + 1] = lp1;
}

__global__ void convert_hl(const float* __restrict__ src,
                           __nv_bfloat16* __restrict__ h,
                           __nv_bfloat16* __restrict__ l, int n4) {
    int i = blockIdx.x * 256 + threadIdx.x;
    if (i >= n4) return;
    split_store(((const float4*)src)[i], h, l, i);
}

struct Cvt4 {
    const float* s[4];
    __nv_bfloat16* h[4];
    __nv_bfloat16* l[4];
};
__global__ void convert_hl4(Cvt4 a, int n4) {
    int w = blockIdx.y;
    int i = blockIdx.x * 256 + threadIdx.x;
    if (i >= n4) return;
    split_store(((const float4*)a.s[w])[i], a.h[w], a.l[w], i);
}

// ---------------------------------------------------------------------------
// Fused aux kernel: blocks 0..63 compute vmean per (b,h); blocks 64..67
// compute gate (c, scale, u) per batch b = blockIdx.x - 64.
// ---------------------------------------------------------------------------
__global__ void aux_kernel(const __nv_bfloat16* __restrict__ Qh,
                           const __nv_bfloat16* __restrict__ Ql,
                           const __nv_bfloat16* __restrict__ Vh,
                           const __nv_bfloat16* __restrict__ Vl,
                           const float* __restrict__ Wg1, const float* __restrict__ bg1,
                           const float* __restrict__ Wg2, const float* __restrict__ bg2,
                           float* __restrict__ vmean,
                           float* __restrict__ c_out, float* __restrict__ scale_out,
                           float* __restrict__ u_out, int write_u) {
    if (blockIdx.x < 64) {
        __shared__ float sm[256];
        int bh = blockIdx.x, tid = threadIdx.x;
        int dk = tid & 63, part = tid >> 6;
        size_t base = (size_t)bh * TT * DKK;
        float s = 0.f;
        for (int t = part; t < TT; t += 4) {
            size_t i = base + (size_t)t * DKK + dk;
            s += __bfloat162float(Vh[i]) + __bfloat162float(Vl[i]);
        }
        sm[tid] = s;
        __syncthreads();
        if (part == 0)
            vmean[bh*DKK + dk] = (sm[dk] + sm[64+dk] + sm[128+dk] + sm[192+dk]) * (1.0f/1024.0f);
        return;
    }
    int b = blockIdx.x - 64;
    float s1 = 0.f, s2 = 0.f;
    for (int d = threadIdx.x; d < DD; d += 256) {
        size_t idx = ((size_t)(b*HH + (d >> 6)))*TT*DKK + (d & 63);
        float q = __bfloat162float(Qh[idx]) + __bfloat162float(Ql[idx]);
        s1 += q * Wg1[d];
        s2 += q * Wg2[d];
    }
#pragma unroll
    for (int off = 16; off >= 1; off >>= 1) {
        s1 += __shfl_xor_sync(0xffffffffu, s1, off);
        s2 += __shfl_xor_sync(0xffffffffu, s2, off);
    }
    __shared__ float r1[8], r2[8];
    int lane = threadIdx.x & 31, w = threadIdx.x >> 5;
    if (lane == 0) { r1[w] = s1; r2[w] = s2; }
    __syncthreads();
    if (threadIdx.x == 0) {
        float t1 = 0.f, t2 = 0.f;
        for (int i = 0; i < 8; i++) { t1 += r1[i]; t2 += r2[i]; }
        float z1 = t1 + bg1[0], z2 = t2 + bg2[0];
        float q1 = 1.f / (1.f + expf(-z1));
        float q2 = 1.f / (1.f + expf(-z2));
        float c = fminf(fmaxf(q1 * q2, 1e-8f), 1.0f);
        float tau = (c < 0.3f) ? (1.0f / c) : 1.0f;
        c_out[b] = c;
        scale_out[b] = 1.0f / (8.0f * tau);
        if (write_u) u_out[b] = 1.0f - c;
    }
}

// ---------------------------------------------------------------------------
// Tensor-core flash attention, register-lean (q-tile 128, 8 warps x 16 rows),
// __launch_bounds__(256, 2) to force 2 CTAs/SM: 4 warps/SMSP so the serial
// softmax chain of one CTA overlaps the MMAs of the other.
// SMEM: Qh@0 (16K), Ql@16K; stages @32K: {Kh,Kl,Vh,Vl} 8K each, 32K/stage x2.
// Total 96K -> 2 CTAs fit in 228K.
// ---------------------------------------------------------------------------
__global__ __launch_bounds__(256, 2)
void attn_mma(const __nv_bfloat16* __restrict__ Qh, const __nv_bfloat16* __restrict__ Ql,
              const __nv_bfloat16* __restrict__ Kh, const __nv_bfloat16* __restrict__ Kl,
              const __nv_bfloat16* __restrict__ Vh, const __nv_bfloat16* __restrict__ Vl,
              const float* __restrict__ vmean,
              const float* __restrict__ c_arr, const float* __restrict__ scale_arr,
              __nv_bfloat16* __restrict__ outH, __nv_bfloat16* __restrict__ outL) {
    extern __shared__ char smem[];
    const int tid = threadIdx.x, wid = tid >> 5, lane = tid & 31;
    const int bh = blockIdx.y;
    const int b = bh >> 4, h = bh & 15;
    const int q0 = blockIdx.x * 128;
    const float scale = scale_arr[b];
    const float cg = c_arr[b];
    const size_t gbase = (size_t)bh * TT * DKK;

    const uint32_t s0 = smem_u32(smem);
    const uint32_t QH = s0, QL = s0 + 16384;
    const uint32_t ST = s0 + 32768;

#pragma unroll
    for (int i = 0; i < 8; i++) {
        int g = tid + i * 256;              // 0..2047
        int arr = g >> 10;                  // 0: Qh, 1: Ql
        int rem = g & 1023;
        int r = rem >> 3, c = rem & 7;
        uint32_t sw = (uint32_t)(r * 128 + ((c ^ (r & 7)) << 4));
        const __nv_bfloat16* src = arr ? Ql : Qh;
        CP_ASYNC16((arr ? QL : QH) + sw, (const char*)(src + gbase + (size_t)(q0 + r) * 64) + c * 16);
    }
#pragma unroll
    for (int i = 0; i < 8; i++) {
        int g = tid + i * 256;              // 0..2047
        int arr = g >> 9;                   // 0:Kh 1:Kl 2:Vh 3:Vl
        int rem = g & 511;
        int r = rem >> 3, c = rem & 7;
        uint32_t sw = (uint32_t)(r * 128 + ((c ^ (r & 7)) << 4));
        const __nv_bfloat16* src = (arr == 0) ? Kh : (arr == 1) ? Kl : (arr == 2) ? Vh : Vl;
        CP_ASYNC16(ST + arr * 8192 + sw, (const char*)(src + gbase + (size_t)r * 64) + c * 16);
    }
    CP_COMMIT();

    const int rA = wid * 16 + (lane & 15);
    const int hA = lane >> 4;
    const int rB = lane & 7;
    const int hB = (lane >> 3) & 1;
    const int rV = lane & 15;

    uint32_t qhF[4][4], qlF[4][4];
    float O[8][4];
    float m0 = -1e30f, m1 = -1e30f, l0 = 0.f, l1 = 0.f;
#pragma unroll
    for (int nt = 0; nt < 8; nt++)
#pragma unroll
        for (int j = 0; j < 4; j++) O[nt][j] = 0.f;

    for (int kt = 0; kt < 16; kt++) {
        const uint32_t stage = ST + (kt & 1) * 32768;
        if (kt + 1 < 16) {
            const uint32_t nstage = ST + ((kt + 1) & 1) * 32768;
            const int k0n = (kt + 1) * 64;
#pragma unroll
            for (int i = 0; i < 8; i++) {
                int g = tid + i * 256;
                int arr = g >> 9;
                int rem = g & 511;
                int r = rem >> 3, c = rem & 7;
                uint32_t sw = (uint32_t)(r * 128 + ((c ^ (r & 7)) << 4));
                const __nv_bfloat16* src = (arr == 0) ? Kh : (arr == 1) ? Kl : (arr == 2) ? Vh : Vl;
                CP_ASYNC16(nstage + arr * 8192 + sw,
                           (const char*)(src + gbase + (size_t)(k0n + r) * 64) + c * 16);
            }
            CP_COMMIT();
            CP_WAIT(1);
        } else {
            CP_WAIT(0);
        }
        __syncthreads();

        if (kt == 0) {
#pragma unroll
            for (int ks = 0; ks < 4; ks++) {
                uint32_t off = (uint32_t)(rA * 128 + (((ks * 2 + hA) ^ (rA & 7)) << 4));
                ldsm_x4(qhF[ks][0], qhF[ks][1], qhF[ks][2], qhF[ks][3], QH + off);
                ldsm_x4(qlF[ks][0], qlF[ks][1], qlF[ks][2], qlF[ks][3], QL + off);
            }
        }

        // ---- S = Q K^T (3-term split) ----
        float sacc[8][4];
#pragma unroll
        for (int nt = 0; nt < 8; nt++)
#pragma unroll
            for (int j = 0; j < 4; j++) sacc[nt][j] = 0.f;

        const uint32_t KHs = stage, KLs = stage + 8192;
#pragma unroll
        for (int ks = 0; ks < 4; ks++) {
#pragma unroll
            for (int nt = 0; nt < 8; nt++) {
                int r = nt * 8 + rB;
                uint32_t off = (uint32_t)(r * 128 + (((ks * 2 + hB) ^ (r & 7)) << 4));
                uint32_t kh[2], kl[2];
                ldsm_x2(kh[0], kh[1], KHs + off);
                ldsm_x2(kl[0], kl[1], KLs + off);
                mma16816(sacc[nt], qhF[ks], kh);
                mma16816(sacc[nt], qhF[ks], kl);
                mma16816(sacc[nt], qlF[ks], kh);
            }
        }

        // ---- online softmax (rows r0 = lane>>2, r1 = r0+8) ----
        float mx0 = -1e30f, mx1 = -1e30f;
#pragma unroll
        for (int nt = 0; nt < 8; nt++) {
            mx0 = fmaxf(mx0, fmaxf(sacc[nt][0], sacc[nt][1]));
            mx1 = fmaxf(mx1, fmaxf(sacc[nt][2], sacc[nt][3]));
        }
        mx0 = fmaxf(mx0, __shfl_xor_sync(0xffffffffu, mx0, 1));
        mx0 = fmaxf(mx0, __shfl_xor_sync(0xffffffffu, mx0, 2));
        mx1 = fmaxf(mx1, __shfl_xor_sync(0xffffffffu, mx1, 1));
        mx1 = fmaxf(mx1, __shfl_xor_sync(0xffffffffu, mx1, 2));
        float mn0 = fmaxf(m0, mx0 * scale);
        float mn1 = fmaxf(m1, mx1 * scale);
        float f0 = __expf(m0 - mn0), f1 = __expf(m1 - mn1);
        m0 = mn0; m1 = mn1;

        float rs0 = 0.f, rs1 = 0.f;
#pragma unroll
        for (int nt = 0; nt < 8; nt++) {
            sacc[nt][0] = __expf(fmaf(sacc[nt][0], scale, -mn0));
            sacc[nt][1] = __expf(fmaf(sacc[nt][1], scale, -mn0));
            sacc[nt][2] = __expf(fmaf(sacc[nt][2], scale, -mn1));
            sacc[nt][3] = __expf(fmaf(sacc[nt][3], scale, -mn1));
            rs0 += sacc[nt][0] + sacc[nt][1];
            rs1 += sacc[nt][2] + sacc[nt][3];
        }
        rs0 += __shfl_xor_sync(0xffffffffu, rs0, 1);
        rs0 += __shfl_xor_sync(0xffffffffu, rs0, 2);
        rs1 += __shfl_xor_sync(0xffffffffu, rs1, 1);
        rs1 += __shfl_xor_sync(0xffffffffu, rs1, 2);
        l0 = l0 * f0 + rs0;
        l1 = l1 * f1 + rs1;
#pragma unroll
        for (int nt = 0; nt < 8; nt++) {
            O[nt][0] *= f0; O[nt][1] *= f0;
            O[nt][2] *= f1; O[nt][3] *= f1;
        }

        // ---- O += P V (3-term split) ----
        const uint32_t VHs = stage + 16384, VLs = stage + 24576;
#pragma unroll
        for (int pk = 0; pk < 4; pk++) {
            uint32_t ph[4], pl[4];
#pragma unroll
            for (int half = 0; half < 2; half++) {
                int nt = 2 * pk + half;
                __nv_bfloat162 a0 = __floats2bfloat162_rn(sacc[nt][0], sacc[nt][1]);
                __nv_bfloat162 a1 = __floats2bfloat162_rn(sacc[nt][2], sacc[nt][3]);
                ph[2*half + 0] = *(uint32_t*)&a0;
                ph[2*half + 1] = *(uint32_t*)&a1;
                __nv_bfloat162 b0 = __floats2bfloat162_rn(
                    sacc[nt][0] - __bfloat162float(a0.x), sacc[nt][1] - __bfloat162float(a0.y));
                __nv_bfloat162 b1 = __floats2bfloat162_rn(
                    sacc[nt][2] - __bfloat162float(a1.x), sacc[nt][3] - __bfloat162float(a1.y));
                pl[2*half + 0] = *(uint32_t*)&b0;
                pl[2*half + 1] = *(uint32_t*)&b1;
            }
            int r = pk * 16 + rV;
#pragma unroll
            for (int nt = 0; nt < 8; nt++) {
                uint32_t off = (uint32_t)(r * 128 + ((nt ^ (r & 7)) << 4));
                uint32_t vh[2], vl[2];
                ldsm_x2t(vh[0], vh[1], VHs + off);
                ldsm_x2t(vl[0], vl[1], VLs + off);
                mma16816(O[nt], ph, vh);
                mma16816(O[nt], ph, vl);
                mma16816(O[nt], pl, vh);
            }
        }
        __syncthreads();
    }

    // ---- epilogue ----
    const float inv0 = 1.0f / l0, inv1 = 1.0f / l1;
    const float omc = 1.0f - cg;
    const int row0 = q0 + wid * 16 + (lane >> 2);
    const int row1 = row0 + 8;
#pragma unroll
    for (int nt = 0; nt < 8; nt++) {
        int dk = nt * 8 + (lane & 3) * 2;
        float vm0 = vmean[bh * DKK + dk], vm1 = vmean[bh * DKK + dk + 1];
        float o00 = cg * O[nt][0] * inv0 + omc * vm0;
        float o01 = cg * O[nt][1] * inv0 + omc * vm1;
        float o10 = cg * O[nt][2] * inv1 + omc * vm0;
        float o11 = cg * O[nt][3] * inv1 + omc * vm1;
        size_t i0 = ((size_t)b * TT + row0) * DD + h * DKK + dk;
        size_t i1 = ((size_t)b * TT + row1) * DD + h * DKK + dk;
        __nv_bfloat162 h0 = __floats2bfloat162_rn(o00, o01);
        __nv_bfloat162 h1 = __floats2bfloat162_rn(o10, o11);
        *(__nv_bfloat162*)(outH + i0) = h0;
        *(__nv_bfloat162*)(outH + i1) = h1;
        *(__nv_bfloat162*)(outL + i0) = __floats2bfloat162_rn(
            o00 - __bfloat162float(h0.x), o01 - __bfloat162float(h0.y));
        *(__nv_bfloat162*)(outL + i1) = __floats2bfloat162_rn(
            o10 - __bfloat162float(h1.x), o11 - __bfloat162float(h1.y));
    }
}

// ---------------------------------------------------------------------------
extern "C" void kernel_launch(void* const* d_in, const int* in_sizes, int n_in,
                              void* d_out, int out_size) {
    const float* x   = (const float*)d_in[0];
    const float* Wq  = (const float*)d_in[1];
    const float* bq  = (const float*)d_in[2];
    const float* Wk  = (const float*)d_in[3];
    const float* bk  = (const float*)d_in[4];
    const float* Wv  = (const float*)d_in[5];
    const float* bv  = (const float*)d_in[6];
    const float* Wo  = (const float*)d_in[7];
    const float* bo  = (const float*)d_in[8];
    const float* Wg1 = (const float*)d_in[9];
    const float* bg1 = (const float*)d_in[10];
    const float* Wg2 = (const float*)d_in[11];
    const float* bg2 = (const float*)d_in[12];
    float* out = (float*)d_out;

    float *pVm, *pC, *pS;
    __nv_bfloat16 *pQh, *pQl, *pKh, *pKl, *pVh, *pVl;
    __nv_bfloat16 *pxh, *pxl, *pWhQ, *pWlQ, *pWhK, *pWlK, *pWhV, *pWlV, *pWhO, *pWlO, *paH, *paL;
    cudaGetSymbolAddress((void**)&pQh, g_Qh);
    cudaGetSymbolAddress((void**)&pQl, g_Ql);
    cudaGetSymbolAddress((void**)&pKh, g_Kh);
    cudaGetSymbolAddress((void**)&pKl, g_Kl);
    cudaGetSymbolAddress((void**)&pVh, g_Vh);
    cudaGetSymbolAddress((void**)&pVl, g_Vl);
    cudaGetSymbolAddress((void**)&pVm, g_vmean);
    cudaGetSymbolAddress((void**)&pC, g_c);
    cudaGetSymbolAddress((void**)&pS, g_scale);
    cudaGetSymbolAddress((void**)&pxh, g_xh);
    cudaGetSymbolAddress((void**)&pxl, g_xl);
    cudaGetSymbolAddress((void**)&pWhQ, g_WhQ);
    cudaGetSymbolAddress((void**)&pWlQ, g_WlQ);
    cudaGetSymbolAddress((void**)&pWhK, g_WhK);
    cudaGetSymbolAddress((void**)&pWlK, g_WlK);
    cudaGetSymbolAddress((void**)&pWhV, g_WhV);
    cudaGetSymbolAddress((void**)&pWlV, g_WlV);
    cudaGetSymbolAddress((void**)&pWhO, g_WhO);
    cudaGetSymbolAddress((void**)&pWlO, g_WlO);
    cudaGetSymbolAddress((void**)&paH, g_aH);
    cudaGetSymbolAddress((void**)&paL, g_aL);

    convert_hl<<<(MROWS*DD/4 + 255)/256, 256>>>(x, pxh, pxl, MROWS*DD/4);
    Cvt4 cw;
    cw.s[0] = Wq; cw.h[0] = pWhQ; cw.l[0] = pWlQ;
    cw.s[1] = Wk; cw.h[1] = pWhK; cw.l[1] = pWlK;
    cw.s[2] = Wv; cw.h[2] = pWhV; cw.l[2] = pWlV;
    cw.s[3] = Wo; cw.h[3] = pWhO; cw.l[3] = pWlO;
    dim3 cvt_grid((DD*DD/4 + 255)/256, 4);
    convert_hl4<<<cvt_grid, 256>>>(cw, DD*DD/4);

    const int GEMM_SMEM = 2 * GSTAGE;   // 196608
    cudaFuncSetAttribute(gemm_mma<1>, cudaFuncAttributeMaxDynamicSharedMemorySize, GEMM_SMEM);
    cudaFuncSetAttribute(gemm_mma<0>, cudaFuncAttributeMaxDynamicSharedMemorySize, GEMM_SMEM);

    GemmArgs qkv = {};
    qkv.Ah = pxh; qkv.Al = pxl;
    qkv.Wh0 = pWhQ; qkv.Wl0 = pWlQ; qkv.Wh1 = pWhK; qkv.Wl1 = pWlK; qkv.Wh2 = pWhV; qkv.Wl2 = pWlV;
    qkv.b0 = bq; qkv.b1 = bk; qkv.b2 = bv;
    qkv.Ch0 = pQh; qkv.Cl0 = pQl; qkv.Ch1 = pKh; qkv.Cl1 = pKl; qkv.Ch2 = pVh; qkv.Cl2 = pVl;
    dim3 qkv_grid(DD/128, MROWS/256, 3);        // (8, 16, 3)
    gemm_mma<1><<<qkv_grid, 256, GEMM_SMEM>>>(qkv);

    int write_u = (out_size >= BB*TT*DD + BB) ? 1 : 0;
    aux_kernel<<<BB*HH + BB, 256>>>(pQh, pQl, pVh, pVl, Wg1, bg1, Wg2, bg2,
                                    pVm, pC, pS, out + (size_t)BB*TT*DD, write_u);

    const int ATTN_SMEM = 32768 + 2 * 32768;    // 98304
    cudaFuncSetAttribute(attn_mma, cudaFuncAttributeMaxDynamicSharedMemorySize, ATTN_SMEM);
    dim3 attn_grid(TT/128, BB*HH);              // (8, 64)
    attn_mma<<<attn_grid, 256, ATTN_SMEM>>>(pQh, pQl, pKh, pKl, pVh, pVl,
                                            pVm, pC, pS, paH, paL);

    GemmArgs oproj = {};
    oproj.Ah = paH; oproj.Al = paL;
    oproj.Wh0 = pWhO; oproj.Wl0 = pWlO; oproj.Wh1 = pWhO; oproj.Wl1 = pWlO; oproj.Wh2 = pWhO; oproj.Wl2 = pWlO;
    oproj.b0 = bo; oproj.b1 = bo; oproj.b2 = bo;
    oproj.C0 = out;
    dim3 o_grid(DD/128, MROWS/256, 1);          // (8, 16, 1)
    gemm_mma<0><<<o_grid, 256, GEMM_SMEM>>>(oproj);
}

// round 11
// speedup vs baseline: 1.5220x; 1.3824x over previous
#include <cuda_runtime.h>
#include <cuda_fp16.h>
#include <math.h>
#include <stdint.h>

#define BB 4
#define TT 1024
#define DD 1024
#define HH 16
#define DKK 64
#define MROWS (BB*TT)   // 4096

// ---------------- scratch (static device globals) ----------------
__device__ __half g_Qh[BB*HH*TT*DKK], g_Ql[BB*HH*TT*DKK];
__device__ __half g_Kh[BB*HH*TT*DKK];
__device__ __half g_Vh[BB*HH*TT*DKK];
__device__ float g_vmean[BB*HH*DKK];
__device__ float g_vpart[256*64];
__device__ float g_c[BB];
__device__ float g_scale[BB];
__device__ __half g_xh[MROWS*DD], g_xl[MROWS*DD];
__device__ __half g_WhQ[DD*DD], g_WhK[DD*DD], g_WhV[DD*DD], g_WhO[DD*DD];
__device__ __half g_aH[MROWS*DD], g_aL[MROWS*DD];

// ---------------- PTX helpers (sm_80-era only) ----------------
__device__ __forceinline__ uint32_t smem_u32(const void* p) {
    uint32_t a;
    asm("{ .reg .u64 t; cvta.to.shared.u64 t, %1; cvt.u32.u64 %0, t; }" : "=r"(a) : "l"(p));
    return a;
}
#define CP_ASYNC16(dst, src) asm volatile("cp.async.cg.shared.global [%0], [%1], 16;" :: "r"(dst), "l"(src))
#define CP_COMMIT()          asm volatile("cp.async.commit_group;" ::: "memory")
#define CP_WAIT(n)           asm volatile("cp.async.wait_group %0;" :: "n"(n) : "memory")

__device__ __forceinline__ void ldsm_x4(uint32_t& r0, uint32_t& r1, uint32_t& r2, uint32_t& r3, uint32_t addr) {
    asm volatile("ldmatrix.sync.aligned.m8n8.x4.shared.b16 {%0,%1,%2,%3}, [%4];"
                 : "=r"(r0), "=r"(r1), "=r"(r2), "=r"(r3) : "r"(addr));
}
__device__ __forceinline__ void ldsm_x2(uint32_t& r0, uint32_t& r1, uint32_t addr) {
    asm volatile("ldmatrix.sync.aligned.m8n8.x2.shared.b16 {%0,%1}, [%2];"
                 : "=r"(r0), "=r"(r1) : "r"(addr));
}
__device__ __forceinline__ void ldsm_x2t(uint32_t& r0, uint32_t& r1, uint32_t addr) {
    asm volatile("ldmatrix.sync.aligned.m8n8.x2.trans.shared.b16 {%0,%1}, [%2];"
                 : "=r"(r0), "=r"(r1) : "r"(addr));
}
__device__ __forceinline__ void mma16816(float* d, const uint32_t* a, const uint32_t* b) {
    asm volatile("mma.sync.aligned.m16n8k16.row.col.f32.f16.f16.f32 "
                 "{%0,%1,%2,%3},{%4,%5,%6,%7},{%8,%9},{%0,%1,%2,%3};"
                 : "+f"(d[0]), "+f"(d[1]), "+f"(d[2]), "+f"(d[3])
                 : "r"(a[0]), "r"(a[1]), "r"(a[2]), "r"(a[3]), "r"(b[0]), "r"(b[1]));
}

// ---------------------------------------------------------------------------
// fp16 2-term GEMM: C[m,n] = sum_k A[m,k]*W[n,k] + bias[n]
// A split (Ah+Al, 22-bit effective); W single fp16.
// CTA 256x128, warp 64x64 (8 warps), BK=64, 2-stage cp.async.
// Stage layout: Ah@0 (32K), Al@32K (32K), Wh@64K (16K). Stage = 80K.
// MODE 0: fp32 rowmajor out.  MODE 1: scatter to [B,H,T,DK]; split if Cl.
// ---------------------------------------------------------------------------
struct GemmArgs {
    const __half *Ah, *Al;
    const __half *Wh0, *Wh1, *Wh2;
    const float *b0, *b1, *b2;
    float *C0;                              // MODE 0
    __half *Ch0, *Cl0, *Ch1, *Cl1, *Ch2, *Cl2; // MODE 1 (Cl may be null)
};

#define GSTAGE 81920

__device__ __forceinline__ void load_stage(uint32_t sbase, int tid,
                                           const __half* Ah, const __half* Al,
                                           const __half* Wh,
                                           int bm, int bn, int k0) {
#pragma unroll
    for (int i = 0; i < 8; i++) {           // A: 256 rows x 8 chunks (x2 arrays)
        int g = tid + i * 256;
        int r = g >> 3, c = g & 7;
        uint32_t sw = (uint32_t)(r * 128 + ((c ^ (r & 7)) << 4));
        size_t ga = (size_t)(bm + r) * 1024 + k0;
        CP_ASYNC16(sbase +     0 + sw, (const char*)(Ah + ga) + c * 16);
        CP_ASYNC16(sbase + 32768 + sw, (const char*)(Al + ga) + c * 16);
    }
#pragma unroll
    for (int i = 0; i < 4; i++) {           // W: 128 rows x 8 chunks
        int g = tid + i * 256;
        int r = g >> 3, c = g & 7;
        uint32_t sw = (uint32_t)(r * 128 + ((c ^ (r & 7)) << 4));
        size_t gw = (size_t)(bn + r) * 1024 + k0;
        CP_ASYNC16(sbase + 65536 + sw, (const char*)(Wh + gw) + c * 16);
    }
}

__device__ __forceinline__ void compute_stage(uint32_t base, int wm, int wn, int lane,
                                              float acc[4][8][4]) {
    const uint32_t aH = base, aL = base + 32768, bH = base + 65536;
    const int rA = wm + (lane & 15);
    const int hA = lane >> 4;
    const int rB = wn + (lane & 7);
    const int hB = (lane >> 3) & 1;
#pragma unroll
    for (int ks = 0; ks < 4; ks++) {
        uint32_t Af[4][4], Alf[4][4], Bf[8][2];
#pragma unroll
        for (int mt = 0; mt < 4; mt++) {
            int r = rA + mt * 16;
            uint32_t off = (uint32_t)(r * 128 + (((ks * 2 + hA) ^ (r & 7)) << 4));
            ldsm_x4(Af[mt][0], Af[mt][1], Af[mt][2], Af[mt][3], aH + off);
            ldsm_x4(Alf[mt][0], Alf[mt][1], Alf[mt][2], Alf[mt][3], aL + off);
        }
#pragma unroll
        for (int nt = 0; nt < 8; nt++) {
            int r = rB + nt * 8;
            uint32_t off = (uint32_t)(r * 128 + (((ks * 2 + hB) ^ (r & 7)) << 4));
            ldsm_x2(Bf[nt][0], Bf[nt][1], bH + off);
        }
#pragma unroll
        for (int mt = 0; mt < 4; mt++)
#pragma unroll
            for (int nt = 0; nt < 8; nt++)
                mma16816(acc[mt][nt], Af[mt], Bf[nt]);
#pragma unroll
        for (int mt = 0; mt < 4; mt++)
#pragma unroll
            for (int nt = 0; nt < 8; nt++)
                mma16816(acc[mt][nt], Alf[mt], Bf[nt]);
    }
}

template<int MODE>
__global__ __launch_bounds__(256)
void gemm_mma(GemmArgs args) {
    extern __shared__ char smem[];
    const int tid = threadIdx.x, wid = tid >> 5, lane = tid & 31;
    const int z = blockIdx.z;
    const __half* Ah = args.Ah;
    const __half* Al = args.Al;
    const __half* Wh = (z == 0) ? args.Wh0 : (z == 1) ? args.Wh1 : args.Wh2;
    const float* bias = (z == 0) ? args.b0 : (z == 1) ? args.b1 : args.b2;
    __half* Ch = (z == 0) ? args.Ch0 : (z == 1) ? args.Ch1 : args.Ch2;
    __half* Cl = (z == 0) ? args.Cl0 : (z == 1) ? args.Cl1 : args.Cl2;

    const int bm = blockIdx.y * 256, bn = blockIdx.x * 128;
    const int wm = (wid >> 1) * 64, wn = (wid & 1) * 64;
    const uint32_t s0 = smem_u32(smem);

    float acc[4][8][4];
#pragma unroll
    for (int a = 0; a < 4; a++)
#pragma unroll
        for (int b = 0; b < 8; b++)
#pragma unroll
            for (int c = 0; c < 4; c++) acc[a][b][c] = 0.f;

    load_stage(s0, tid, Ah, Al, Wh, bm, bn, 0);
    CP_COMMIT();

    for (int kt = 0; kt < 16; kt++) {
        if (kt + 1 < 16) {
            load_stage(s0 + ((kt + 1) & 1) * GSTAGE, tid, Ah, Al, Wh, bm, bn, (kt + 1) * 64);
            CP_COMMIT();
            CP_WAIT(1);
        } else {
            CP_WAIT(0);
        }
        __syncthreads();
        compute_stage(s0 + (kt & 1) * GSTAGE, wm, wn, lane, acc);
        __syncthreads();
    }

    const int lr = lane >> 2, lc = (lane & 3) * 2;
#pragma unroll
    for (int mt = 0; mt < 4; mt++) {
#pragma unroll
        for (int nt = 0; nt < 8; nt++) {
            int c0 = bn + wn + nt * 8 + lc;
            float b0 = __ldg(bias + c0), b1 = __ldg(bias + c0 + 1);
            int r0 = bm + wm + mt * 16 + lr;
            int r1 = r0 + 8;
            float v00 = acc[mt][nt][0] + b0, v01 = acc[mt][nt][1] + b1;
            float v10 = acc[mt][nt][2] + b0, v11 = acc[mt][nt][3] + b1;
            if (MODE == 0) {
                *(float2*)(args.C0 + (size_t)r0 * 1024 + c0) = make_float2(v00, v01);
                *(float2*)(args.C0 + (size_t)r1 * 1024 + c0) = make_float2(v10, v11);
            } else {
                int h = c0 >> 6, dk = c0 & 63;
                size_t i0 = (((size_t)((r0 >> 10) * HH + h)) * TT + (r0 & 1023)) * DKK + dk;
                size_t i1 = (((size_t)((r1 >> 10) * HH + h)) * TT + (r1 & 1023)) * DKK + dk;
                __half2 h0 = __floats2half2_rn(v00, v01);
                __half2 h1 = __floats2half2_rn(v10, v11);
                *(__half2*)(Ch + i0) = h0;
                *(__half2*)(Ch + i1) = h1;
                if (Cl) {
                    *(__half2*)(Cl + i0) = __floats2half2_rn(
                        v00 - __low2float(h0), v01 - __high2float(h0));
                    *(__half2*)(Cl + i1) = __floats2half2_rn(
                        v10 - __low2float(h1), v11 - __high2float(h1));
                }
            }
        }
    }
}

// ---------------------------------------------------------------------------
// Conversions
// ---------------------------------------------------------------------------
__global__ void convert_xsplit(const float* __restrict__ src,
                               __half* __restrict__ h,
                               __half* __restrict__ l, int n4) {
    int i = blockIdx.x * 256 + threadIdx.x;
    if (i >= n4) return;
    float4 v = ((const float4*)src)[i];
    __half2 h0 = __floats2half2_rn(v.x, v.y);
    __half2 h1 = __floats2half2_rn(v.z, v.w);
    ((__half2*)h)[i * 2 + 0] = h0;
    ((__half2*)h)[i * 2 + 1] = h1;
    ((__half2*)l)[i * 2 + 0] = __floats2half2_rn(v.x - __low2float(h0), v.y - __high2float(h0));
    ((__half2*)l)[i * 2 + 1] = __floats2half2_rn(v.z - __low2float(h1), v.w - __high2float(h1));
}

struct CvtW { const float* s[4]; __half* h[4]; };
__global__ void convert_w4(CvtW a, int n4) {
    int w = blockIdx.y;
    int i = blockIdx.x * 256 + threadIdx.x;
    if (i >= n4) return;
    float4 v = ((const float4*)a.s[w])[i];
    ((__half2*)a.h[w])[i * 2 + 0] = __floats2half2_rn(v.x, v.y);
    ((__half2*)a.h[w])[i * 2 + 1] = __floats2half2_rn(v.z, v.w);
}

// ---------------------------------------------------------------------------
// vmean phase 1: 256 blocks, each sums a 256-row quarter of one (b,h).
// ---------------------------------------------------------------------------
__global__ void vmean_part(const __half* __restrict__ Vh, float* __restrict__ vpart) {
    __shared__ float sm[256];
    int blk = blockIdx.x;               // 0..255
    int bh = blk >> 2, q = blk & 3;
    int tid = threadIdx.x, dk = tid & 63, part = tid >> 6;
    size_t base = (size_t)bh * TT * DKK;
    float s = 0.f;
    for (int t = q * 256 + part; t < q * 256 + 256; t += 4)
        s += __half2float(Vh[base + (size_t)t * DKK + dk]);
    sm[tid] = s;
    __syncthreads();
    if (part == 0)
        vpart[blk * 64 + dk] = sm[dk] + sm[64+dk] + sm[128+dk] + sm[192+dk];
}

// ---------------------------------------------------------------------------
// aux: blocks 0..63 combine vmean partials; blocks 64..67 gate.
// ---------------------------------------------------------------------------
__global__ void aux_final(const __half* __restrict__ Qh, const __half* __restrict__ Ql,
                          const float* __restrict__ vpart,
                          const float* __restrict__ Wg1, const float* __restrict__ bg1,
                          const float* __restrict__ Wg2, const float* __restrict__ bg2,
                          float* __restrict__ vmean,
                          float* __restrict__ c_out, float* __restrict__ scale_out,
                          float* __restrict__ u_out, int write_u) {
    if (blockIdx.x < 64) {
        int bh = blockIdx.x, dk = threadIdx.x;
        if (dk < 64) {
            float s = vpart[(bh*4+0)*64 + dk] + vpart[(bh*4+1)*64 + dk]
                    + vpart[(bh*4+2)*64 + dk] + vpart[(bh*4+3)*64 + dk];
            vmean[bh * 64 + dk] = s * (1.0f / 1024.0f);
        }
        return;
    }
    int b = blockIdx.x - 64;
    float s1 = 0.f, s2 = 0.f;
    for (int d = threadIdx.x; d < DD; d += 256) {
        size_t idx = ((size_t)(b*HH + (d >> 6)))*TT*DKK + (d & 63);
        float q = __half2float(Qh[idx]) + __half2float(Ql[idx]);
        s1 += q * Wg1[d];
        s2 += q * Wg2[d];
    }
#pragma unroll
    for (int off = 16; off >= 1; off >>= 1) {
        s1 += __shfl_xor_sync(0xffffffffu, s1, off);
        s2 += __shfl_xor_sync(0xffffffffu, s2, off);
    }
    __shared__ float r1[8], r2[8];
    int lane = threadIdx.x & 31, w = threadIdx.x >> 5;
    if (lane == 0) { r1[w] = s1; r2[w] = s2; }
    __syncthreads();
    if (threadIdx.x == 0) {
        float t1 = 0.f, t2 = 0.f;
        for (int i = 0; i < 8; i++) { t1 += r1[i]; t2 += r2[i]; }
        float z1 = t1 + bg1[0], z2 = t2 + bg2[0];
        float q1 = 1.f / (1.f + expf(-z1));
        float q2 = 1.f / (1.f + expf(-z2));
        float c = fminf(fmaxf(q1 * q2, 1e-8f), 1.0f);
        float tau = (c < 0.3f) ? (1.0f / c) : 1.0f;
        c_out[b] = c;
        scale_out[b] = 1.0f / (8.0f * tau);
        if (write_u) u_out[b] = 1.0f - c;
    }
}

// ---------------------------------------------------------------------------
// fp16 2-term flash attention. Block = 128 queries x (b,h). 8 warps x 16 rows.
// S = (Qh+Ql)·Kh (2 MMAs); O += (Ph+Pl)·Vh (2 MMAs). K/V single fp16.
// SMEM: Qh@0 (16K), Ql@16K; stages @32K: {Kh 8K, Vh 8K} = 16K/stage x2. 64K.
// ---------------------------------------------------------------------------
__global__ __launch_bounds__(256, 2)
void attn_mma(const __half* __restrict__ Qh, const __half* __restrict__ Ql,
              const __half* __restrict__ Kh, const __half* __restrict__ Vh,
              const float* __restrict__ vmean,
              const float* __restrict__ c_arr, const float* __restrict__ scale_arr,
              __half* __restrict__ outH, __half* __restrict__ outL) {
    extern __shared__ char smem[];
    const int tid = threadIdx.x, wid = tid >> 5, lane = tid & 31;
    const int bh = blockIdx.y;
    const int b = bh >> 4, h = bh & 15;
    const int q0 = blockIdx.x * 128;
    const float scale = scale_arr[b];
    const float cg = c_arr[b];
    const size_t gbase = (size_t)bh * TT * DKK;

    const uint32_t s0 = smem_u32(smem);
    const uint32_t QH = s0, QL = s0 + 16384;
    const uint32_t ST = s0 + 32768;

    // Q tile: 2 arrays x 128 rows x 8 chunks = 2048 chunks
#pragma unroll
    for (int i = 0; i < 8; i++) {
        int g = tid + i * 256;
        int arr = g >> 10;
        int rem = g & 1023;
        int r = rem >> 3, c = rem & 7;
        uint32_t sw = (uint32_t)(r * 128 + ((c ^ (r & 7)) << 4));
        const __half* src = arr ? Ql : Qh;
        CP_ASYNC16((arr ? QL : QH) + sw, (const char*)(src + gbase + (size_t)(q0 + r) * 64) + c * 16);
    }
    // KV stage 0: 2 arrays x 64 rows x 8 chunks = 1024 chunks
#pragma unroll
    for (int i = 0; i < 4; i++) {
        int g = tid + i * 256;
        int arr = g >> 9;                   // 0:Kh 1:Vh
        int rem = g & 511;
        int r = rem >> 3, c = rem & 7;
        uint32_t sw = (uint32_t)(r * 128 + ((c ^ (r & 7)) << 4));
        const __half* src = arr ? Vh : Kh;
        CP_ASYNC16(ST + arr * 8192 + sw, (const char*)(src + gbase + (size_t)r * 64) + c * 16);
    }
    CP_COMMIT();

    const int rA = wid * 16 + (lane & 15);
    const int hA = lane >> 4;
    const int rB = lane & 7;
    const int hB = (lane >> 3) & 1;
    const int rV = lane & 15;

    uint32_t qhF[4][4], qlF[4][4];
    float O[8][4];
    float m0 = -1e30f, m1 = -1e30f, l0 = 0.f, l1 = 0.f;
#pragma unroll
    for (int nt = 0; nt < 8; nt++)
#pragma unroll
        for (int j = 0; j < 4; j++) O[nt][j] = 0.f;

    for (int kt = 0; kt < 16; kt++) {
        const uint32_t stage = ST + (kt & 1) * 16384;
        if (kt + 1 < 16) {
            const uint32_t nstage = ST + ((kt + 1) & 1) * 16384;
            const int k0n = (kt + 1) * 64;
#pragma unroll
            for (int i = 0; i < 4; i++) {
                int g = tid + i * 256;
                int arr = g >> 9;
                int rem = g & 511;
                int r = rem >> 3, c = rem & 7;
                uint32_t sw = (uint32_t)(r * 128 + ((c ^ (r & 7)) << 4));
                const __half* src = arr ? Vh : Kh;
                CP_ASYNC16(nstage + arr * 8192 + sw,
                           (const char*)(src + gbase + (size_t)(k0n + r) * 64) + c * 16);
            }
            CP_COMMIT();
            CP_WAIT(1);
        } else {
            CP_WAIT(0);
        }
        __syncthreads();

        if (kt == 0) {
#pragma unroll
            for (int ks = 0; ks < 4; ks++) {
                uint32_t off = (uint32_t)(rA * 128 + (((ks * 2 + hA) ^ (rA & 7)) << 4));
                ldsm_x4(qhF[ks][0], qhF[ks][1], qhF[ks][2], qhF[ks][3], QH + off);
                ldsm_x4(qlF[ks][0], qlF[ks][1], qlF[ks][2], qlF[ks][3], QL + off);
            }
        }

        // ---- S = (Qh+Ql)·Kh ----
        float sacc[8][4];
#pragma unroll
        for (int nt = 0; nt < 8; nt++)
#pragma unroll
            for (int j = 0; j < 4; j++) sacc[nt][j] = 0.f;

        const uint32_t KHs = stage;
#pragma unroll
        for (int ks = 0; ks < 4; ks++) {
#pragma unroll
            for (int nt = 0; nt < 8; nt++) {
                int r = nt * 8 + rB;
                uint32_t off = (uint32_t)(r * 128 + (((ks * 2 + hB) ^ (r & 7)) << 4));
                uint32_t kh[2];
                ldsm_x2(kh[0], kh[1], KHs + off);
                mma16816(sacc[nt], qhF[ks], kh);
                mma16816(sacc[nt], qlF[ks], kh);
            }
        }

        // ---- online softmax (rows r0 = lane>>2, r1 = r0+8) ----
        float mx0 = -1e30f, mx1 = -1e30f;
#pragma unroll
        for (int nt = 0; nt < 8; nt++) {
            mx0 = fmaxf(mx0, fmaxf(sacc[nt][0], sacc[nt][1]));
            mx1 = fmaxf(mx1, fmaxf(sacc[nt][2], sacc[nt][3]));
        }
        mx0 = fmaxf(mx0, __shfl_xor_sync(0xffffffffu, mx0, 1));
        mx0 = fmaxf(mx0, __shfl_xor_sync(0xffffffffu, mx0, 2));
        mx1 = fmaxf(mx1, __shfl_xor_sync(0xffffffffu, mx1, 1));
        mx1 = fmaxf(mx1, __shfl_xor_sync(0xffffffffu, mx1, 2));
        float mn0 = fmaxf(m0, mx0 * scale);
        float mn1 = fmaxf(m1, mx1 * scale);
        float f0 = __expf(m0 - mn0), f1 = __expf(m1 - mn1);
        m0 = mn0; m1 = mn1;

        float rs0 = 0.f, rs1 = 0.f;
#pragma unroll
        for (int nt = 0; nt < 8; nt++) {
            sacc[nt][0] = __expf(fmaf(sacc[nt][0], scale, -mn0));
            sacc[nt][1] = __expf(fmaf(sacc[nt][1], scale, -mn0));
            sacc[nt][2] = __expf(fmaf(sacc[nt][2], scale, -mn1));
            sacc[nt][3] = __expf(fmaf(sacc[nt][3], scale, -mn1));
            rs0 += sacc[nt][0] + sacc[nt][1];
            rs1 += sacc[nt][2] + sacc[nt][3];
        }
        rs0 += __shfl_xor_sync(0xffffffffu, rs0, 1);
        rs0 += __shfl_xor_sync(0xffffffffu, rs0, 2);
        rs1 += __shfl_xor_sync(0xffffffffu, rs1, 1);
        rs1 += __shfl_xor_sync(0xffffffffu, rs1, 2);
        l0 = l0 * f0 + rs0;
        l1 = l1 * f1 + rs1;
#pragma unroll
        for (int nt = 0; nt < 8; nt++) {
            O[nt][0] *= f0; O[nt][1] *= f0;
            O[nt][2] *= f1; O[nt][3] *= f1;
        }

        // ---- O += (Ph+Pl)·Vh ----
        const uint32_t VHs = stage + 8192;
#pragma unroll
        for (int pk = 0; pk < 4; pk++) {
            uint32_t ph[4], pl[4];
#pragma unroll
            for (int half_ = 0; half_ < 2; half_++) {
                int nt = 2 * pk + half_;
                __half2 a0 = __floats2half2_rn(sacc[nt][0], sacc[nt][1]);
                __half2 a1 = __floats2half2_rn(sacc[nt][2], sacc[nt][3]);
                ph[2*half_ + 0] = *(uint32_t*)&a0;
                ph[2*half_ + 1] = *(uint32_t*)&a1;
                __half2 b0 = __floats2half2_rn(
                    sacc[nt][0] - __low2float(a0), sacc[nt][1] - __high2float(a0));
                __half2 b1 = __floats2half2_rn(
                    sacc[nt][2] - __low2float(a1), sacc[nt][3] - __high2float(a1));
                pl[2*half_ + 0] = *(uint32_t*)&b0;
                pl[2*half_ + 1] = *(uint32_t*)&b1;
            }
            int r = pk * 16 + rV;
#pragma unroll
            for (int nt = 0; nt < 8; nt++) {
                uint32_t off = (uint32_t)(r * 128 + ((nt ^ (r & 7)) << 4));
                uint32_t vh[2];
                ldsm_x2t(vh[0], vh[1], VHs + off);
                mma16816(O[nt], ph, vh);
                mma16816(O[nt], pl, vh);
            }
        }
        __syncthreads();
    }

    // ---- epilogue: gate + vmean, fp16 split output for O-projection ----
    const float inv0 = 1.0f / l0, inv1 = 1.0f / l1;
    const float omc = 1.0f - cg;
    const int row0 = q0 + wid * 16 + (lane >> 2);
    const int row1 = row0 + 8;
#pragma unroll
    for (int nt = 0; nt < 8; nt++) {
        int dk = nt * 8 + (lane & 3) * 2;
        float vm0 = vmean[bh * DKK + dk], vm1 = vmean[bh * DKK + dk + 1];
        float o00 = cg * O[nt][0] * inv0 + omc * vm0;
        float o01 = cg * O[nt][1] * inv0 + omc * vm1;
        float o10 = cg * O[nt][2] * inv1 + omc * vm0;
        float o11 = cg * O[nt][3] * inv1 + omc * vm1;
        size_t i0 = ((size_t)b * TT + row0) * DD + h * DKK + dk;
        size_t i1 = ((size_t)b * TT + row1) * DD + h * DKK + dk;
        __half2 h0 = __floats2half2_rn(o00, o01);
        __half2 h1 = __floats2half2_rn(o10, o11);
        *(__half2*)(outH + i0) = h0;
        *(__half2*)(outH + i1) = h1;
        *(__half2*)(outL + i0) = __floats2half2_rn(
            o00 - __low2float(h0), o01 - __high2float(h0));
        *(__half2*)(outL + i1) = __floats2half2_rn(
            o10 - __low2float(h1), o11 - __high2float(h1));
    }
}

// ---------------------------------------------------------------------------
extern "C" void kernel_launch(void* const* d_in, const int* in_sizes, int n_in,
                              void* d_out, int out_size) {
    const float* x   = (const float*)d_in[0];
    const float* Wq  = (const float*)d_in[1];
    const float* bq  = (const float*)d_in[2];
    const float* Wk  = (const float*)d_in[3];
    const float* bk  = (const float*)d_in[4];
    const float* Wv  = (const float*)d_in[5];
    const float* bv  = (const float*)d_in[6];
    const float* Wo  = (const float*)d_in[7];
    const float* bo  = (const float*)d_in[8];
    const float* Wg1 = (const float*)d_in[9];
    const float* bg1 = (const float*)d_in[10];
    const float* Wg2 = (const float*)d_in[11];
    const float* bg2 = (const float*)d_in[12];
    float* out = (float*)d_out;

    float *pVm, *pVp, *pC, *pS;
    __half *pQh, *pQl, *pKh, *pVh;
    __half *pxh, *pxl, *pWhQ, *pWhK, *pWhV, *pWhO, *paH, *paL;
    cudaGetSymbolAddress((void**)&pQh, g_Qh);
    cudaGetSymbolAddress((void**)&pQl, g_Ql);
    cudaGetSymbolAddress((void**)&pKh, g_Kh);
    cudaGetSymbolAddress((void**)&pVh, g_Vh);
    cudaGetSymbolAddress((void**)&pVm, g_vmean);
    cudaGetSymbolAddress((void**)&pVp, g_vpart);
    cudaGetSymbolAddress((void**)&pC, g_c);
    cudaGetSymbolAddress((void**)&pS, g_scale);
    cudaGetSymbolAddress((void**)&pxh, g_xh);
    cudaGetSymbolAddress((void**)&pxl, g_xl);
    cudaGetSymbolAddress((void**)&pWhQ, g_WhQ);
    cudaGetSymbolAddress((void**)&pWhK, g_WhK);
    cudaGetSymbolAddress((void**)&pWhV, g_WhV);
    cudaGetSymbolAddress((void**)&pWhO, g_WhO);
    cudaGetSymbolAddress((void**)&paH, g_aH);
    cudaGetSymbolAddress((void**)&paL, g_aL);

    convert_xsplit<<<(MROWS*DD/4 + 255)/256, 256>>>(x, pxh, pxl, MROWS*DD/4);
    CvtW cw;
    cw.s[0] = Wq; cw.h[0] = pWhQ;
    cw.s[1] = Wk; cw.h[1] = pWhK;
    cw.s[2] = Wv; cw.h[2] = pWhV;
    cw.s[3] = Wo; cw.h[3] = pWhO;
    dim3 cvt_grid((DD*DD/4 + 255)/256, 4);
    convert_w4<<<cvt_grid, 256>>>(cw, DD*DD/4);

    const int GEMM_SMEM = 2 * GSTAGE;   // 163840
    cudaFuncSetAttribute(gemm_mma<1>, cudaFuncAttributeMaxDynamicSharedMemorySize, GEMM_SMEM);
    cudaFuncSetAttribute(gemm_mma<0>, cudaFuncAttributeMaxDynamicSharedMemorySize, GEMM_SMEM);

    GemmArgs qkv = {};
    qkv.Ah = pxh; qkv.Al = pxl;
    qkv.Wh0 = pWhQ; qkv.Wh1 = pWhK; qkv.Wh2 = pWhV;
    qkv.b0 = bq; qkv.b1 = bk; qkv.b2 = bv;
    qkv.Ch0 = pQh; qkv.Cl0 = pQl;       // Q split (A operand of S)
    qkv.Ch1 = pKh; qkv.Cl1 = nullptr;   // K single fp16
    qkv.Ch2 = pVh; qkv.Cl2 = nullptr;   // V single fp16
    dim3 qkv_grid(DD/128, MROWS/256, 3);        // (8, 16, 3)
    gemm_mma<1><<<qkv_grid, 256, GEMM_SMEM>>>(qkv);

    vmean_part<<<256, 256>>>(pVh, pVp);
    int write_u = (out_size >= BB*TT*DD + BB) ? 1 : 0;
    aux_final<<<BB*HH + BB, 256>>>(pQh, pQl, pVp, Wg1, bg1, Wg2, bg2,
                                   pVm, pC, pS, out + (size_t)BB*TT*DD, write_u);

    const int ATTN_SMEM = 32768 + 2 * 16384;    // 65536
    cudaFuncSetAttribute(attn_mma, cudaFuncAttributeMaxDynamicSharedMemorySize, ATTN_SMEM);
    dim3 attn_grid(TT/128, BB*HH);              // (8, 64)
    attn_mma<<<attn_grid, 256, ATTN_SMEM>>>(pQh, pQl, pKh, pVh,
                                            pVm, pC, pS, paH, paL);

    GemmArgs oproj = {};
    oproj.Ah = paH; oproj.Al = paL;
    oproj.Wh0 = pWhO; oproj.Wh1 = pWhO; oproj.Wh2 = pWhO;
    oproj.b0 = bo; oproj.b1 = bo; oproj.b2 = bo;
    oproj.C0 = out;
    dim3 o_grid(DD/128, MROWS/256, 1);          // (8, 16, 1)
    gemm_mma<0><<<o_grid, 256, GEMM_SMEM>>>(oproj);
}

// round 12
// speedup vs baseline: 2.4370x; 1.6012x over previous
#include <cuda_runtime.h>
#include <cuda_fp16.h>
#include <math.h>
#include <stdint.h>

#define BB 4
#define TT 1024
#define DD 1024
#define HH 16
#define DKK 64
#define MROWS (BB*TT)   // 4096

// ---------------- scratch (static device globals) ----------------
__device__ __half g_Q[BB*HH*TT*DKK];
__device__ __half g_K[BB*HH*TT*DKK];
__device__ __half g_V[BB*HH*TT*DKK];
__device__ float g_vmean[BB*HH*DKK];
__device__ float g_vpart[256*64];
__device__ float g_c[BB];
__device__ float g_scale[BB];
__device__ __half g_x16[MROWS*DD];
__device__ __half g_WhQ[DD*DD], g_WhK[DD*DD], g_WhV[DD*DD], g_WhO[DD*DD];
__device__ __half g_a16[MROWS*DD];

// ---------------- PTX helpers (sm_80-era only) ----------------
__device__ __forceinline__ uint32_t smem_u32(const void* p) {
    uint32_t a;
    asm("{ .reg .u64 t; cvta.to.shared.u64 t, %1; cvt.u32.u64 %0, t; }" : "=r"(a) : "l"(p));
    return a;
}
#define CP_ASYNC16(dst, src) asm volatile("cp.async.cg.shared.global [%0], [%1], 16;" :: "r"(dst), "l"(src))
#define CP_COMMIT()          asm volatile("cp.async.commit_group;" ::: "memory")
#define CP_WAIT(n)           asm volatile("cp.async.wait_group %0;" :: "n"(n) : "memory")

__device__ __forceinline__ void ldsm_x4(uint32_t& r0, uint32_t& r1, uint32_t& r2, uint32_t& r3, uint32_t addr) {
    asm volatile("ldmatrix.sync.aligned.m8n8.x4.shared.b16 {%0,%1,%2,%3}, [%4];"
                 : "=r"(r0), "=r"(r1), "=r"(r2), "=r"(r3) : "r"(addr));
}
__device__ __forceinline__ void ldsm_x2(uint32_t& r0, uint32_t& r1, uint32_t addr) {
    asm volatile("ldmatrix.sync.aligned.m8n8.x2.shared.b16 {%0,%1}, [%2];"
                 : "=r"(r0), "=r"(r1) : "r"(addr));
}
__device__ __forceinline__ void ldsm_x2t(uint32_t& r0, uint32_t& r1, uint32_t addr) {
    asm volatile("ldmatrix.sync.aligned.m8n8.x2.trans.shared.b16 {%0,%1}, [%2];"
                 : "=r"(r0), "=r"(r1) : "r"(addr));
}
__device__ __forceinline__ void mma16816(float* d, const uint32_t* a, const uint32_t* b) {
    asm volatile("mma.sync.aligned.m16n8k16.row.col.f32.f16.f16.f32 "
                 "{%0,%1,%2,%3},{%4,%5,%6,%7},{%8,%9},{%0,%1,%2,%3};"
                 : "+f"(d[0]), "+f"(d[1]), "+f"(d[2]), "+f"(d[3])
                 : "r"(a[0]), "r"(a[1]), "r"(a[2]), "r"(a[3]), "r"(b[0]), "r"(b[1]));
}

// ---------------------------------------------------------------------------
// Single-fp16 GEMM: C[m,n] = sum_k A[m,k]*W[n,k] + bias[n]
// CTA 256x128, warp 64x64 (8 warps), BK=64, 2-stage cp.async.
// Stage layout: A@0 (32K), W@32K (16K). Stage = 48K; 2 stages = 96K.
// MODE 0: fp32 rowmajor out.  MODE 1: fp16 scatter to [B,H,T,DK].
// ---------------------------------------------------------------------------
struct GemmArgs {
    const __half *A;
    const __half *Wh0, *Wh1, *Wh2;
    const float *b0, *b1, *b2;
    float *C0;                   // MODE 0
    __half *Ch0, *Ch1, *Ch2;     // MODE 1
};

#define GSTAGE 49152

__device__ __forceinline__ void load_stage(uint32_t sbase, int tid,
                                           const __half* A, const __half* Wh,
                                           int bm, int bn, int k0) {
#pragma unroll
    for (int i = 0; i < 8; i++) {           // A: 256 rows x 8 chunks
        int g = tid + i * 256;
        int r = g >> 3, c = g & 7;
        uint32_t sw = (uint32_t)(r * 128 + ((c ^ (r & 7)) << 4));
        CP_ASYNC16(sbase + sw, (const char*)(A + (size_t)(bm + r) * 1024 + k0) + c * 16);
    }
#pragma unroll
    for (int i = 0; i < 4; i++) {           // W: 128 rows x 8 chunks
        int g = tid + i * 256;
        int r = g >> 3, c = g & 7;
        uint32_t sw = (uint32_t)(r * 128 + ((c ^ (r & 7)) << 4));
        CP_ASYNC16(sbase + 32768 + sw, (const char*)(Wh + (size_t)(bn + r) * 1024 + k0) + c * 16);
    }
}

__device__ __forceinline__ void compute_stage(uint32_t base, int wm, int wn, int lane,
                                              float acc[4][8][4]) {
    const uint32_t aS = base, bS = base + 32768;
    const int rA = wm + (lane & 15);
    const int hA = lane >> 4;
    const int rB = wn + (lane & 7);
    const int hB = (lane >> 3) & 1;
#pragma unroll
    for (int ks = 0; ks < 4; ks++) {
        uint32_t Af[4][4], Bf[8][2];
#pragma unroll
        for (int mt = 0; mt < 4; mt++) {
            int r = rA + mt * 16;
            uint32_t off = (uint32_t)(r * 128 + (((ks * 2 + hA) ^ (r & 7)) << 4));
            ldsm_x4(Af[mt][0], Af[mt][1], Af[mt][2], Af[mt][3], aS + off);
        }
#pragma unroll
        for (int nt = 0; nt < 8; nt++) {
            int r = rB + nt * 8;
            uint32_t off = (uint32_t)(r * 128 + (((ks * 2 + hB) ^ (r & 7)) << 4));
            ldsm_x2(Bf[nt][0], Bf[nt][1], bS + off);
        }
#pragma unroll
        for (int mt = 0; mt < 4; mt++)
#pragma unroll
            for (int nt = 0; nt < 8; nt++)
                mma16816(acc[mt][nt], Af[mt], Bf[nt]);
    }
}

template<int MODE>
__global__ __launch_bounds__(256)
void gemm_mma(GemmArgs args) {
    extern __shared__ char smem[];
    const int tid = threadIdx.x, wid = tid >> 5, lane = tid & 31;
    const int z = blockIdx.z;
    const __half* A = args.A;
    const __half* Wh = (z == 0) ? args.Wh0 : (z == 1) ? args.Wh1 : args.Wh2;
    const float* bias = (z == 0) ? args.b0 : (z == 1) ? args.b1 : args.b2;
    __half* Ch = (z == 0) ? args.Ch0 : (z == 1) ? args.Ch1 : args.Ch2;

    const int bm = blockIdx.y * 256, bn = blockIdx.x * 128;
    const int wm = (wid >> 1) * 64, wn = (wid & 1) * 64;
    const uint32_t s0 = smem_u32(smem);

    float acc[4][8][4];
#pragma unroll
    for (int a = 0; a < 4; a++)
#pragma unroll
        for (int b = 0; b < 8; b++)
#pragma unroll
            for (int c = 0; c < 4; c++) acc[a][b][c] = 0.f;

    load_stage(s0, tid, A, Wh, bm, bn, 0);
    CP_COMMIT();

    for (int kt = 0; kt < 16; kt++) {
        if (kt + 1 < 16) {
            load_stage(s0 + ((kt + 1) & 1) * GSTAGE, tid, A, Wh, bm, bn, (kt + 1) * 64);
            CP_COMMIT();
            CP_WAIT(1);
        } else {
            CP_WAIT(0);
        }
        __syncthreads();
        compute_stage(s0 + (kt & 1) * GSTAGE, wm, wn, lane, acc);
        __syncthreads();
    }

    const int lr = lane >> 2, lc = (lane & 3) * 2;
#pragma unroll
    for (int mt = 0; mt < 4; mt++) {
#pragma unroll
        for (int nt = 0; nt < 8; nt++) {
            int c0 = bn + wn + nt * 8 + lc;
            float b0 = __ldg(bias + c0), b1 = __ldg(bias + c0 + 1);
            int r0 = bm + wm + mt * 16 + lr;
            int r1 = r0 + 8;
            float v00 = acc[mt][nt][0] + b0, v01 = acc[mt][nt][1] + b1;
            float v10 = acc[mt][nt][2] + b0, v11 = acc[mt][nt][3] + b1;
            if (MODE == 0) {
                *(float2*)(args.C0 + (size_t)r0 * 1024 + c0) = make_float2(v00, v01);
                *(float2*)(args.C0 + (size_t)r1 * 1024 + c0) = make_float2(v10, v11);
            } else {
                int h = c0 >> 6, dk = c0 & 63;
                size_t i0 = (((size_t)((r0 >> 10) * HH + h)) * TT + (r0 & 1023)) * DKK + dk;
                size_t i1 = (((size_t)((r1 >> 10) * HH + h)) * TT + (r1 & 1023)) * DKK + dk;
                *(__half2*)(Ch + i0) = __floats2half2_rn(v00, v01);
                *(__half2*)(Ch + i1) = __floats2half2_rn(v10, v11);
            }
        }
    }
}

// ---------------------------------------------------------------------------
// Conversions
// ---------------------------------------------------------------------------
__global__ void convert_f16(const float* __restrict__ src,
                            __half* __restrict__ h, int n4) {
    int i = blockIdx.x * 256 + threadIdx.x;
    if (i >= n4) return;
    float4 v = ((const float4*)src)[i];
    ((__half2*)h)[i * 2 + 0] = __floats2half2_rn(v.x, v.y);
    ((__half2*)h)[i * 2 + 1] = __floats2half2_rn(v.z, v.w);
}

struct CvtW { const float* s[4]; __half* h[4]; };
__global__ void convert_w4(CvtW a, int n4) {
    int w = blockIdx.y;
    int i = blockIdx.x * 256 + threadIdx.x;
    if (i >= n4) return;
    float4 v = ((const float4*)a.s[w])[i];
    ((__half2*)a.h[w])[i * 2 + 0] = __floats2half2_rn(v.x, v.y);
    ((__half2*)a.h[w])[i * 2 + 1] = __floats2half2_rn(v.z, v.w);
}

// ---------------------------------------------------------------------------
// vmean phase 1: 256 blocks, each sums a 256-row quarter of one (b,h).
// ---------------------------------------------------------------------------
__global__ void vmean_part(const __half* __restrict__ Vh, float* __restrict__ vpart) {
    __shared__ float sm[256];
    int blk = blockIdx.x;
    int bh = blk >> 2, q = blk & 3;
    int tid = threadIdx.x, dk = tid & 63, part = tid >> 6;
    size_t base = (size_t)bh * TT * DKK;
    float s = 0.f;
    for (int t = q * 256 + part; t < q * 256 + 256; t += 4)
        s += __half2float(Vh[base + (size_t)t * DKK + dk]);
    sm[tid] = s;
    __syncthreads();
    if (part == 0)
        vpart[blk * 64 + dk] = sm[dk] + sm[64+dk] + sm[128+dk] + sm[192+dk];
}

// ---------------------------------------------------------------------------
// aux: blocks 0..63 combine vmean partials; blocks 64..67 gate.
// ---------------------------------------------------------------------------
__global__ void aux_final(const __half* __restrict__ Q,
                          const float* __restrict__ vpart,
                          const float* __restrict__ Wg1, const float* __restrict__ bg1,
                          const float* __restrict__ Wg2, const float* __restrict__ bg2,
                          float* __restrict__ vmean,
                          float* __restrict__ c_out, float* __restrict__ scale_out,
                          float* __restrict__ u_out, int write_u) {
    if (blockIdx.x < 64) {
        int bh = blockIdx.x, dk = threadIdx.x;
        if (dk < 64) {
            float s = vpart[(bh*4+0)*64 + dk] + vpart[(bh*4+1)*64 + dk]
                    + vpart[(bh*4+2)*64 + dk] + vpart[(bh*4+3)*64 + dk];
            vmean[bh * 64 + dk] = s * (1.0f / 1024.0f);
        }
        return;
    }
    int b = blockIdx.x - 64;
    float s1 = 0.f, s2 = 0.f;
    for (int d = threadIdx.x; d < DD; d += 256) {
        size_t idx = ((size_t)(b*HH + (d >> 6)))*TT*DKK + (d & 63);
        float q = __half2float(Q[idx]);
        s1 += q * Wg1[d];
        s2 += q * Wg2[d];
    }
#pragma unroll
    for (int off = 16; off >= 1; off >>= 1) {
        s1 += __shfl_xor_sync(0xffffffffu, s1, off);
        s2 += __shfl_xor_sync(0xffffffffu, s2, off);
    }
    __shared__ float r1[8], r2[8];
    int lane = threadIdx.x & 31, w = threadIdx.x >> 5;
    if (lane == 0) { r1[w] = s1; r2[w] = s2; }
    __syncthreads();
    if (threadIdx.x == 0) {
        float t1 = 0.f, t2 = 0.f;
        for (int i = 0; i < 8; i++) { t1 += r1[i]; t2 += r2[i]; }
        float z1 = t1 + bg1[0], z2 = t2 + bg2[0];
        float q1 = 1.f / (1.f + expf(-z1));
        float q2 = 1.f / (1.f + expf(-z2));
        float c = fminf(fmaxf(q1 * q2, 1e-8f), 1.0f);
        float tau = (c < 0.3f) ? (1.0f / c) : 1.0f;
        c_out[b] = c;
        scale_out[b] = 1.0f / (8.0f * tau);
        if (write_u) u_out[b] = 1.0f - c;
    }
}

// ---------------------------------------------------------------------------
// Single-fp16 flash attention. Block = 128 queries x (b,h). 8 warps x 16 rows.
// SMEM: Q@0 (16K); stages @16K: {K 8K, V 8K} = 16K/stage x2. Total 48K.
// ---------------------------------------------------------------------------
__global__ __launch_bounds__(256, 2)
void attn_mma(const __half* __restrict__ Qg,
              const __half* __restrict__ Kg, const __half* __restrict__ Vg,
              const float* __restrict__ vmean,
              const float* __restrict__ c_arr, const float* __restrict__ scale_arr,
              __half* __restrict__ outA) {
    extern __shared__ char smem[];
    const int tid = threadIdx.x, wid = tid >> 5, lane = tid & 31;
    const int bh = blockIdx.y;
    const int b = bh >> 4, h = bh & 15;
    const int q0 = blockIdx.x * 128;
    const float scale = scale_arr[b];
    const float cg = c_arr[b];
    const size_t gbase = (size_t)bh * TT * DKK;

    const uint32_t s0 = smem_u32(smem);
    const uint32_t QS = s0;
    const uint32_t ST = s0 + 16384;

    // Q tile: 128 rows x 8 chunks = 1024 chunks
#pragma unroll
    for (int i = 0; i < 4; i++) {
        int g = tid + i * 256;
        int r = g >> 3, c = g & 7;
        uint32_t sw = (uint32_t)(r * 128 + ((c ^ (r & 7)) << 4));
        CP_ASYNC16(QS + sw, (const char*)(Qg + gbase + (size_t)(q0 + r) * 64) + c * 16);
    }
    // KV stage 0: 2 arrays x 64 rows x 8 chunks = 1024 chunks
#pragma unroll
    for (int i = 0; i < 4; i++) {
        int g = tid + i * 256;
        int arr = g >> 9;
        int rem = g & 511;
        int r = rem >> 3, c = rem & 7;
        uint32_t sw = (uint32_t)(r * 128 + ((c ^ (r & 7)) << 4));
        const __half* src = arr ? Vg : Kg;
        CP_ASYNC16(ST + arr * 8192 + sw, (const char*)(src + gbase + (size_t)r * 64) + c * 16);
    }
    CP_COMMIT();

    const int rA = wid * 16 + (lane & 15);
    const int hA = lane >> 4;
    const int rB = lane & 7;
    const int hB = (lane >> 3) & 1;
    const int rV = lane & 15;

    uint32_t qF[4][4];
    float O[8][4];
    float m0 = -1e30f, m1 = -1e30f, l0 = 0.f, l1 = 0.f;
#pragma unroll
    for (int nt = 0; nt < 8; nt++)
#pragma unroll
        for (int j = 0; j < 4; j++) O[nt][j] = 0.f;

    for (int kt = 0; kt < 16; kt++) {
        const uint32_t stage = ST + (kt & 1) * 16384;
        if (kt + 1 < 16) {
            const uint32_t nstage = ST + ((kt + 1) & 1) * 16384;
            const int k0n = (kt + 1) * 64;
#pragma unroll
            for (int i = 0; i < 4; i++) {
                int g = tid + i * 256;
                int arr = g >> 9;
                int rem = g & 511;
                int r = rem >> 3, c = rem & 7;
                uint32_t sw = (uint32_t)(r * 128 + ((c ^ (r & 7)) << 4));
                const __half* src = arr ? Vg : Kg;
                CP_ASYNC16(nstage + arr * 8192 + sw,
                           (const char*)(src + gbase + (size_t)(k0n + r) * 64) + c * 16);
            }
            CP_COMMIT();
            CP_WAIT(1);
        } else {
            CP_WAIT(0);
        }
        __syncthreads();

        if (kt == 0) {
#pragma unroll
            for (int ks = 0; ks < 4; ks++) {
                uint32_t off = (uint32_t)(rA * 128 + (((ks * 2 + hA) ^ (rA & 7)) << 4));
                ldsm_x4(qF[ks][0], qF[ks][1], qF[ks][2], qF[ks][3], QS + off);
            }
        }

        // ---- S = Q·K ----
        float sacc[8][4];
#pragma unroll
        for (int nt = 0; nt < 8; nt++)
#pragma unroll
            for (int j = 0; j < 4; j++) sacc[nt][j] = 0.f;

#pragma unroll
        for (int ks = 0; ks < 4; ks++) {
#pragma unroll
            for (int nt = 0; nt < 8; nt++) {
                int r = nt * 8 + rB;
                uint32_t off = (uint32_t)(r * 128 + (((ks * 2 + hB) ^ (r & 7)) << 4));
                uint32_t kf[2];
                ldsm_x2(kf[0], kf[1], stage + off);
                mma16816(sacc[nt], qF[ks], kf);
            }
        }

        // ---- online softmax (rows r0 = lane>>2, r1 = r0+8) ----
        float mx0 = -1e30f, mx1 = -1e30f;
#pragma unroll
        for (int nt = 0; nt < 8; nt++) {
            mx0 = fmaxf(mx0, fmaxf(sacc[nt][0], sacc[nt][1]));
            mx1 = fmaxf(mx1, fmaxf(sacc[nt][2], sacc[nt][3]));
        }
        mx0 = fmaxf(mx0, __shfl_xor_sync(0xffffffffu, mx0, 1));
        mx0 = fmaxf(mx0, __shfl_xor_sync(0xffffffffu, mx0, 2));
        mx1 = fmaxf(mx1, __shfl_xor_sync(0xffffffffu, mx1, 1));
        mx1 = fmaxf(mx1, __shfl_xor_sync(0xffffffffu, mx1, 2));
        float mn0 = fmaxf(m0, mx0 * scale);
        float mn1 = fmaxf(m1, mx1 * scale);
        float f0 = __expf(m0 - mn0), f1 = __expf(m1 - mn1);
        m0 = mn0; m1 = mn1;

        float rs0 = 0.f, rs1 = 0.f;
#pragma unroll
        for (int nt = 0; nt < 8; nt++) {
            sacc[nt][0] = __expf(fmaf(sacc[nt][0], scale, -mn0));
            sacc[nt][1] = __expf(fmaf(sacc[nt][1], scale, -mn0));
            sacc[nt][2] = __expf(fmaf(sacc[nt][2], scale, -mn1));
            sacc[nt][3] = __expf(fmaf(sacc[nt][3], scale, -mn1));
            rs0 += sacc[nt][0] + sacc[nt][1];
            rs1 += sacc[nt][2] + sacc[nt][3];
        }
        rs0 += __shfl_xor_sync(0xffffffffu, rs0, 1);
        rs0 += __shfl_xor_sync(0xffffffffu, rs0, 2);
        rs1 += __shfl_xor_sync(0xffffffffu, rs1, 1);
        rs1 += __shfl_xor_sync(0xffffffffu, rs1, 2);
        l0 = l0 * f0 + rs0;
        l1 = l1 * f1 + rs1;
#pragma unroll
        for (int nt = 0; nt < 8; nt++) {
            O[nt][0] *= f0; O[nt][1] *= f0;
            O[nt][2] *= f1; O[nt][3] *= f1;
        }

        // ---- O += P·V ----
        const uint32_t VHs = stage + 8192;
#pragma unroll
        for (int pk = 0; pk < 4; pk++) {
            uint32_t ph[4];
#pragma unroll
            for (int half_ = 0; half_ < 2; half_++) {
                int nt = 2 * pk + half_;
                __half2 a0 = __floats2half2_rn(sacc[nt][0], sacc[nt][1]);
                __half2 a1 = __floats2half2_rn(sacc[nt][2], sacc[nt][3]);
                ph[2*half_ + 0] = *(uint32_t*)&a0;
                ph[2*half_ + 1] = *(uint32_t*)&a1;
            }
            int r = pk * 16 + rV;
#pragma unroll
            for (int nt = 0; nt < 8; nt++) {
                uint32_t off = (uint32_t)(r * 128 + ((nt ^ (r & 7)) << 4));
                uint32_t vf[2];
                ldsm_x2t(vf[0], vf[1], VHs + off);
                mma16816(O[nt], ph, vf);
            }
        }
        __syncthreads();
    }

    // ---- epilogue: gate + vmean, fp16 output for O-projection ----
    const float inv0 = 1.0f / l0, inv1 = 1.0f / l1;
    const float omc = 1.0f - cg;
    const int row0 = q0 + wid * 16 + (lane >> 2);
    const int row1 = row0 + 8;
#pragma unroll
    for (int nt = 0; nt < 8; nt++) {
        int dk = nt * 8 + (lane & 3) * 2;
        float vm0 = vmean[bh * DKK + dk], vm1 = vmean[bh * DKK + dk + 1];
        float o00 = cg * O[nt][0] * inv0 + omc * vm0;
        float o01 = cg * O[nt][1] * inv0 + omc * vm1;
        float o10 = cg * O[nt][2] * inv1 + omc * vm0;
        float o11 = cg * O[nt][3] * inv1 + omc * vm1;
        size_t i0 = ((size_t)b * TT + row0) * DD + h * DKK + dk;
        size_t i1 = ((size_t)b * TT + row1) * DD + h * DKK + dk;
        *(__half2*)(outA + i0) = __floats2half2_rn(o00, o01);
        *(__half2*)(outA + i1) = __floats2half2_rn(o10, o11);
    }
}

// ---------------------------------------------------------------------------
extern "C" void kernel_launch(void* const* d_in, const int* in_sizes, int n_in,
                              void* d_out, int out_size) {
    const float* x   = (const float*)d_in[0];
    const float* Wq  = (const float*)d_in[1];
    const float* bq  = (const float*)d_in[2];
    const float* Wk  = (const float*)d_in[3];
    const float* bk  = (const float*)d_in[4];
    const float* Wv  = (const float*)d_in[5];
    const float* bv  = (const float*)d_in[6];
    const float* Wo  = (const float*)d_in[7];
    const float* bo  = (const float*)d_in[8];
    const float* Wg1 = (const float*)d_in[9];
    const float* bg1 = (const float*)d_in[10];
    const float* Wg2 = (const float*)d_in[11];
    const float* bg2 = (const float*)d_in[12];
    float* out = (float*)d_out;

    float *pVm, *pVp, *pC, *pS;
    __half *pQ, *pK, *pV, *px16, *pWhQ, *pWhK, *pWhV, *pWhO, *pa16;
    cudaGetSymbolAddress((void**)&pQ, g_Q);
    cudaGetSymbolAddress((void**)&pK, g_K);
    cudaGetSymbolAddress((void**)&pV, g_V);
    cudaGetSymbolAddress((void**)&pVm, g_vmean);
    cudaGetSymbolAddress((void**)&pVp, g_vpart);
    cudaGetSymbolAddress((void**)&pC, g_c);
    cudaGetSymbolAddress((void**)&pS, g_scale);
    cudaGetSymbolAddress((void**)&px16, g_x16);
    cudaGetSymbolAddress((void**)&pWhQ, g_WhQ);
    cudaGetSymbolAddress((void**)&pWhK, g_WhK);
    cudaGetSymbolAddress((void**)&pWhV, g_WhV);
    cudaGetSymbolAddress((void**)&pWhO, g_WhO);
    cudaGetSymbolAddress((void**)&pa16, g_a16);

    convert_f16<<<(MROWS*DD/4 + 255)/256, 256>>>(x, px16, MROWS*DD/4);
    CvtW cw;
    cw.s[0] = Wq; cw.h[0] = pWhQ;
    cw.s[1] = Wk; cw.h[1] = pWhK;
    cw.s[2] = Wv; cw.h[2] = pWhV;
    cw.s[3] = Wo; cw.h[3] = pWhO;
    dim3 cvt_grid((DD*DD/4 + 255)/256, 4);
    convert_w4<<<cvt_grid, 256>>>(cw, DD*DD/4);

    const int GEMM_SMEM = 2 * GSTAGE;   // 98304
    cudaFuncSetAttribute(gemm_mma<1>, cudaFuncAttributeMaxDynamicSharedMemorySize, GEMM_SMEM);
    cudaFuncSetAttribute(gemm_mma<0>, cudaFuncAttributeMaxDynamicSharedMemorySize, GEMM_SMEM);

    GemmArgs qkv = {};
    qkv.A = px16;
    qkv.Wh0 = pWhQ; qkv.Wh1 = pWhK; qkv.Wh2 = pWhV;
    qkv.b0 = bq; qkv.b1 = bk; qkv.b2 = bv;
    qkv.Ch0 = pQ; qkv.Ch1 = pK; qkv.Ch2 = pV;
    dim3 qkv_grid(DD/128, MROWS/256, 3);        // (8, 16, 3)
    gemm_mma<1><<<qkv_grid, 256, GEMM_SMEM>>>(qkv);

    vmean_part<<<256, 256>>>(pV, pVp);
    int write_u = (out_size >= BB*TT*DD + BB) ? 1 : 0;
    aux_final<<<BB*HH + BB, 256>>>(pQ, pVp, Wg1, bg1, Wg2, bg2,
                                   pVm, pC, pS, out + (size_t)BB*TT*DD, write_u);

    const int ATTN_SMEM = 16384 + 2 * 16384;    // 49152
    cudaFuncSetAttribute(attn_mma, cudaFuncAttributeMaxDynamicSharedMemorySize, ATTN_SMEM);
    dim3 attn_grid(TT/128, BB*HH);              // (8, 64)
    attn_mma<<<attn_grid, 256, ATTN_SMEM>>>(pQ, pK, pV, pVm, pC, pS, pa16);

    GemmArgs oproj = {};
    oproj.A = pa16;
    oproj.Wh0 = pWhO; oproj.Wh1 = pWhO; oproj.Wh2 = pWhO;
    oproj.b0 = bo; oproj.b1 = bo; oproj.b2 = bo;
    oproj.C0 = out;
    dim3 o_grid(DD/128, MROWS/256, 1);          // (8, 16, 1)
    gemm_mma<0><<<o_grid, 256, GEMM_SMEM>>>(oproj);
}